// round 7
// baseline (speedup 1.0000x reference)
#include <cuda_runtime.h>
#include <cuda_fp16.h>
#include <cstdint>

// ---------------------------------------------------------------------------
// PerceiverAttention, sm_103 — Round 6:
//   * gemm_tc: __launch_bounds__(256,1) — kill register spills (128 acc regs
//     no longer squeezed under a 128-reg cap), 4-stage cp.async pipeline
// ---------------------------------------------------------------------------

#define BATCH 8
#define N1 4096
#define N2 64
#define NKEYS 4160
#define DIM 1024
#define HEADS 16
#define DH 64
#define MROWS (BATCH * NKEYS)   // 33280
#define NSPLIT 5
#define CH_PER_SPLIT 13

__device__ __half g_kvin[(size_t)MROWS * DIM];
__device__ __half g_lnh [(size_t)BATCH * N2 * DIM];
__device__ float  g_q   [(size_t)BATCH * N2 * DIM];
__device__ __half g_kvh [(size_t)MROWS * 2 * DIM];
__device__ __half g_attnh[(size_t)BATCH * N2 * DIM];
__device__ __half g_wkvT[(size_t)2 * DIM * DIM];
__device__ __half g_wqT [(size_t)DIM * DIM];
__device__ __half g_woT [(size_t)DIM * DIM];
__device__ float  g_pO  [(size_t)BATCH * HEADS * NSPLIT * N2 * DH];
__device__ float  g_pml [(size_t)BATCH * HEADS * NSPLIT * 2 * N2];

// ---------------------------------------------------------------------------
// Helpers
// ---------------------------------------------------------------------------
__device__ __forceinline__ uint32_t smem_u32(const void* p) {
    uint32_t a;
    asm("{ .reg .u64 t; cvta.to.shared.u64 t, %1; cvt.u32.u64 %0, t; }" : "=r"(a) : "l"(p));
    return a;
}
__device__ __forceinline__ void cp_async16(uint32_t dst, const void* src) {
    asm volatile("cp.async.cg.shared.global [%0], [%1], 16;" :: "r"(dst), "l"(src));
}
__device__ __forceinline__ void cp_commit() {
    asm volatile("cp.async.commit_group;" ::: "memory");
}
template <int N>
__device__ __forceinline__ void cp_wait() {
    asm volatile("cp.async.wait_group %0;" :: "n"(N) : "memory");
}
__device__ __forceinline__ void mma_f16(float* d, const uint32_t* a, const uint32_t* b) {
    asm volatile(
        "mma.sync.aligned.m16n8k16.row.col.f32.f16.f16.f32 "
        "{%0,%1,%2,%3}, {%4,%5,%6,%7}, {%8,%9}, {%0,%1,%2,%3};"
        : "+f"(d[0]), "+f"(d[1]), "+f"(d[2]), "+f"(d[3])
        : "r"(a[0]), "r"(a[1]), "r"(a[2]), "r"(a[3]), "r"(b[0]), "r"(b[1]));
}
__device__ __forceinline__ void ldm_x4(uint32_t* r, uint32_t addr) {
    asm volatile("ldmatrix.sync.aligned.m8n8.x4.shared.b16 {%0,%1,%2,%3}, [%4];"
        : "=r"(r[0]), "=r"(r[1]), "=r"(r[2]), "=r"(r[3]) : "r"(addr));
}
__device__ __forceinline__ void store_pair(float* p, float a, float b) {
    *reinterpret_cast<float2*>(p) = make_float2(a, b);
}
__device__ __forceinline__ void store_pair(__half* p, float a, float b) {
    *reinterpret_cast<__half2*>(p) = make_half2(__float2half_rn(a), __float2half_rn(b));
}

// ---------------------------------------------------------------------------
// Weight transpose + fp16 round
// ---------------------------------------------------------------------------
__global__ __launch_bounds__(256) void transpose_kernel(
    const float* __restrict__ in, __half* __restrict__ out, int ncols)
{
    __shared__ float t[32][33];
    const int bx = blockIdx.x * 32;
    const int by = blockIdx.y * 32;
    const int x = threadIdx.x;
    const int y = threadIdx.y;
    #pragma unroll
    for (int i = 0; i < 32; i += 8)
        t[y + i][x] = in[(size_t)(by + y + i) * ncols + bx + x];
    __syncthreads();
    #pragma unroll
    for (int i = 0; i < 32; i += 8)
        out[(size_t)(bx + y + i) * DIM + by + x] = __float2half_rn(t[x][y + i]);
}

// ---------------------------------------------------------------------------
// LayerNorm -> half outputs
// ---------------------------------------------------------------------------
__global__ __launch_bounds__(256) void ln_kernel(
    const float* __restrict__ x, const float* __restrict__ lat,
    const float* __restrict__ g1, const float* __restrict__ b1,
    const float* __restrict__ g2, const float* __restrict__ b2)
{
    __shared__ float red[16];
    const int r  = blockIdx.x;
    const int bb = r / NKEYS;
    const int i  = r - bb * NKEYS;

    const float* src;
    const float* g;
    const float* be;
    __half* dst2 = nullptr;
    if (i < N1) {
        src = x + ((size_t)bb * N1 + i) * DIM;
        g = g1; be = b1;
    } else {
        const int j = i - N1;
        src = lat + ((size_t)bb * N2 + j) * DIM;
        g = g2; be = b2;
        dst2 = g_lnh + ((size_t)bb * N2 + j) * DIM;
    }
    __half* dst = g_kvin + (size_t)r * DIM;

    const int t = threadIdx.x;
    float4 v = reinterpret_cast<const float4*>(src)[t];
    float s  = v.x + v.y + v.z + v.w;
    float sq = v.x * v.x + v.y * v.y + v.z * v.z + v.w * v.w;
    #pragma unroll
    for (int o = 16; o > 0; o >>= 1) {
        s  += __shfl_xor_sync(0xffffffffu, s, o);
        sq += __shfl_xor_sync(0xffffffffu, sq, o);
    }
    if ((t & 31) == 0) { red[t >> 5] = s; red[8 + (t >> 5)] = sq; }
    __syncthreads();
    float S = 0.f, SQ = 0.f;
    #pragma unroll
    for (int k = 0; k < 8; k++) { S += red[k]; SQ += red[8 + k]; }

    const float mu   = S * (1.0f / DIM);
    const float var  = SQ * (1.0f / DIM) - mu * mu;
    const float rstd = rsqrtf(var + 1e-5f);

    float4 gv = reinterpret_cast<const float4*>(g)[t];
    float4 bv = reinterpret_cast<const float4*>(be)[t];
    __half2 h0 = make_half2(__float2half_rn((v.x - mu) * rstd * gv.x + bv.x),
                            __float2half_rn((v.y - mu) * rstd * gv.y + bv.y));
    __half2 h1 = make_half2(__float2half_rn((v.z - mu) * rstd * gv.z + bv.z),
                            __float2half_rn((v.w - mu) * rstd * gv.w + bv.w));
    reinterpret_cast<__half2*>(dst)[t * 2]     = h0;
    reinterpret_cast<__half2*>(dst)[t * 2 + 1] = h1;
    if (dst2) {
        reinterpret_cast<__half2*>(dst2)[t * 2]     = h0;
        reinterpret_cast<__half2*>(dst2)[t * 2 + 1] = h1;
    }
}

// ---------------------------------------------------------------------------
// fp16 mma.sync GEMM, ldmatrix fragments, 4-stage cp.async pipeline,
// NO register cap (1 CTA/SM) so the 128 accumulators never spill.
// ---------------------------------------------------------------------------
#define PADH 72
#define TILE_H (128 * PADH)
#define NSTAGE 4
#define GEMM_SMEM_BYTES (NSTAGE * 2 * TILE_H * 2)   // 147456

template <typename OutT>
__global__ __launch_bounds__(256, 1) void gemm_tc(
    const __half* __restrict__ A, const __half* __restrict__ Bt,
    OutT* __restrict__ C, int ldc)
{
    extern __shared__ __half smh[];
    const uint32_t sb = smem_u32(smh);

    const int tid  = threadIdx.x;
    const int wid  = tid >> 5;
    const int lane = tid & 31;
    const int wm = wid & 3;
    const int wn = wid >> 2;
    const int m0 = blockIdx.y * 128;
    const int n0 = blockIdx.x * 128;

    const __half* ga = A  + (size_t)m0 * DIM;
    const __half* gb = Bt + (size_t)n0 * DIM;

    const int lr = tid >> 3;
    const int lc = tid & 7;

    float acc[2][8][4];
    #pragma unroll
    for (int i = 0; i < 2; i++)
        #pragma unroll
        for (int j = 0; j < 8; j++)
            #pragma unroll
            for (int q = 0; q < 4; q++) acc[i][j][q] = 0.f;

    const uint32_t a_off = (uint32_t)(wm * 32 + (lane & 15)) * PADH + (lane >> 4) * 8;
    const uint32_t b_off = (uint32_t)(wn * 64 + ((lane >> 4) << 3) + (lane & 7)) * PADH
                         + ((lane >> 3) & 1) * 8;

    auto load_tile = [&](int chunk, int stage) {
        const uint32_t abase = sb + (uint32_t)stage * 2 * TILE_H * 2;
        const uint32_t bbase = abase + TILE_H * 2;
        const int k0 = chunk * 64;
        #pragma unroll
        for (int i = 0; i < 4; i++) {
            const int r = lr + i * 32;
            cp_async16(abase + (r * PADH + lc * 8) * 2, ga + (size_t)r * DIM + k0 + lc * 8);
        }
        #pragma unroll
        for (int i = 0; i < 4; i++) {
            const int r = lr + i * 32;
            cp_async16(bbase + (r * PADH + lc * 8) * 2, gb + (size_t)r * DIM + k0 + lc * 8);
        }
        cp_commit();
    };

    const int NCHUNK = DIM / 64;   // 16
    load_tile(0, 0);
    load_tile(1, 1);
    load_tile(2, 2);

    for (int c = 0; c < NCHUNK; c++) {
        const int stage = c & 3;
        if (c + 3 < NCHUNK)       { load_tile(c + 3, (c + 3) & 3); cp_wait<3>(); }
        else if (c + 3 == NCHUNK) { cp_wait<2>(); }
        else if (c + 2 == NCHUNK) { cp_wait<1>(); }
        else                      { cp_wait<0>(); }
        __syncthreads();

        const uint32_t sA = sb + (uint32_t)stage * 2 * TILE_H * 2;
        const uint32_t sB = sA + TILE_H * 2;

        #pragma unroll
        for (int kk = 0; kk < 4; kk++) {
            uint32_t af[2][4], bf[8][2];
            #pragma unroll
            for (int mt = 0; mt < 2; mt++)
                ldm_x4(af[mt], sA + (a_off + (uint32_t)(mt * 16) * PADH + kk * 16) * 2);
            #pragma unroll
            for (int p = 0; p < 4; p++) {
                uint32_t r4[4];
                ldm_x4(r4, sB + (b_off + (uint32_t)(p * 16) * PADH + kk * 16) * 2);
                bf[2 * p][0]     = r4[0];
                bf[2 * p][1]     = r4[1];
                bf[2 * p + 1][0] = r4[2];
                bf[2 * p + 1][1] = r4[3];
            }
            #pragma unroll
            for (int mt = 0; mt < 2; mt++)
                #pragma unroll
                for (int nt = 0; nt < 8; nt++)
                    mma_f16(acc[mt][nt], af[mt], bf[nt]);
        }
        __syncthreads();
    }

    #pragma unroll
    for (int mt = 0; mt < 2; mt++) {
        const int row = m0 + wm * 32 + mt * 16 + (lane >> 2);
        #pragma unroll
        for (int nt = 0; nt < 8; nt++) {
            const int col = n0 + wn * 64 + nt * 8 + (lane & 3) * 2;
            store_pair(C + (size_t)row * ldc + col, acc[mt][nt][0], acc[mt][nt][1]);
            store_pair(C + (size_t)(row + 8) * ldc + col, acc[mt][nt][2], acc[mt][nt][3]);
        }
    }
}

// ---------------------------------------------------------------------------
// Split-K flash attention (fp32 compute; KV loaded as half)
// ---------------------------------------------------------------------------
__global__ __launch_bounds__(256) void attn_partial(const float* __restrict__ mask)
{
    __shared__ float qs_t[64 * 64];
    __shared__ float ks_t[64 * 64];
    __shared__ float vs  [64 * 64];

    const int h = blockIdx.x;
    const int b = blockIdx.y;
    const int sp = blockIdx.z;
    const int bh = b * HEADS + h;
    const int tid = threadIdx.x;
    const int tq = tid >> 4;
    const int tx = tid & 15;

    {
        const int qr = tid >> 2;
        const int dg = tid & 3;
        const float4* src = reinterpret_cast<const float4*>(
            g_q + ((size_t)(b * N2 + qr)) * DIM + h * DH + dg * 16);
        #pragma unroll
        for (int ii = 0; ii < 4; ii++) {
            float4 v = src[ii];
            const int d0 = dg * 16 + ii * 4;
            qs_t[(d0 + 0) * 64 + qr] = v.x * 0.125f;
            qs_t[(d0 + 1) * 64 + qr] = v.y * 0.125f;
            qs_t[(d0 + 2) * 64 + qr] = v.z * 0.125f;
            qs_t[(d0 + 3) * 64 + qr] = v.w * 0.125f;
        }
    }

    float O[4][4] = {};
    float m[4], l[4];
    #pragma unroll
    for (int i = 0; i < 4; i++) { m[i] = -1e30f; l[i] = 0.f; }

    const size_t kvbase = (size_t)b * NKEYS * (2 * DIM);

    for (int cc = 0; cc < CH_PER_SPLIT; cc++) {
        const int key0 = (sp * CH_PER_SPLIT + cc) * 64;
        __syncthreads();

        {
            const int kl = tid >> 2;
            const int dg = tid & 3;
            const uint4* ksrc = reinterpret_cast<const uint4*>(
                g_kvh + kvbase + (size_t)(key0 + kl) * (2 * DIM) + h * DH + dg * 16);
            #pragma unroll
            for (int part = 0; part < 2; part++) {
                uint4 u = ksrc[part];
                const __half2* hp = reinterpret_cast<const __half2*>(&u);
                const int d0 = dg * 16 + part * 8;
                #pragma unroll
                for (int j = 0; j < 4; j++) {
                    float2 f = __half22float2(hp[j]);
                    ks_t[(d0 + 2 * j) * 64 + kl]     = f.x;
                    ks_t[(d0 + 2 * j + 1) * 64 + kl] = f.y;
                }
            }
            const uint4* vsrc = reinterpret_cast<const uint4*>(
                g_kvh + kvbase + (size_t)(key0 + kl) * (2 * DIM) + DIM + h * DH + dg * 16);
            #pragma unroll
            for (int part = 0; part < 2; part++) {
                uint4 u = vsrc[part];
                const __half2* hp = reinterpret_cast<const __half2*>(&u);
                const int d0 = dg * 16 + part * 8;
                #pragma unroll
                for (int j = 0; j < 4; j++) {
                    float2 f = __half22float2(hp[j]);
                    vs[kl * 64 + d0 + 2 * j]     = f.x;
                    vs[kl * 64 + d0 + 2 * j + 1] = f.y;
                }
            }
        }
        __syncthreads();

        float acc[4][4] = {};
        #pragma unroll 8
        for (int d = 0; d < 64; d++) {
            float4 av = *reinterpret_cast<const float4*>(qs_t + d * 64 + tq * 4);
            float4 bv = *reinterpret_cast<const float4*>(ks_t + d * 64 + tx * 4);
            float a[4] = {av.x, av.y, av.z, av.w};
            float kb[4] = {bv.x, bv.y, bv.z, bv.w};
            #pragma unroll
            for (int i = 0; i < 4; i++)
                #pragma unroll
                for (int j = 0; j < 4; j++)
                    acc[i][j] += a[i] * kb[j];
        }

        #pragma unroll
        for (int j = 0; j < 4; j++) {
            const int kg = key0 + tx * 4 + j;
            float bias = 0.f;
            if (kg < N1) bias = (mask[(size_t)b * N1 + kg] - 1.0f) * 100.0f;
            #pragma unroll
            for (int i = 0; i < 4; i++) acc[i][j] += bias;
        }

        float alpha[4];
        #pragma unroll
        for (int i = 0; i < 4; i++) {
            float cm = fmaxf(fmaxf(acc[i][0], acc[i][1]), fmaxf(acc[i][2], acc[i][3]));
            #pragma unroll
            for (int o = 1; o < 16; o <<= 1)
                cm = fmaxf(cm, __shfl_xor_sync(0xffffffffu, cm, o));
            const float mn = fmaxf(m[i], cm);
            alpha[i] = __expf(m[i] - mn);
            float cl = 0.f;
            #pragma unroll
            for (int j = 0; j < 4; j++) {
                const float p = __expf(acc[i][j] - mn);
                acc[i][j] = p;
                cl += p;
            }
            #pragma unroll
            for (int o = 1; o < 16; o <<= 1)
                cl += __shfl_xor_sync(0xffffffffu, cl, o);
            l[i] = l[i] * alpha[i] + cl;
            m[i] = mn;
            #pragma unroll
            for (int j = 0; j < 4; j++) O[i][j] *= alpha[i];
        }

        __syncthreads();
        #pragma unroll
        for (int i = 0; i < 4; i++)
            #pragma unroll
            for (int j = 0; j < 4; j++)
                ks_t[(tq * 4 + i) * 64 + tx * 4 + j] = acc[i][j];
        __syncthreads();

        #pragma unroll 8
        for (int k = 0; k < 64; k++) {
            float p0 = ks_t[(tq * 4 + 0) * 64 + k];
            float p1 = ks_t[(tq * 4 + 1) * 64 + k];
            float p2 = ks_t[(tq * 4 + 2) * 64 + k];
            float p3 = ks_t[(tq * 4 + 3) * 64 + k];
            float4 vv = *reinterpret_cast<const float4*>(vs + k * 64 + tx * 4);
            float v4[4] = {vv.x, vv.y, vv.z, vv.w};
            #pragma unroll
            for (int j = 0; j < 4; j++) {
                O[0][j] += p0 * v4[j];
                O[1][j] += p1 * v4[j];
                O[2][j] += p2 * v4[j];
                O[3][j] += p3 * v4[j];
            }
        }
    }

    float* po = g_pO + ((size_t)(bh * NSPLIT + sp) * N2) * DH;
    #pragma unroll
    for (int i = 0; i < 4; i++) {
        *reinterpret_cast<float4*>(po + (size_t)(tq * 4 + i) * DH + tx * 4) =
            make_float4(O[i][0], O[i][1], O[i][2], O[i][3]);
    }
    if (tx == 0) {
        float* pml = g_pml + (size_t)(bh * NSPLIT + sp) * 2 * N2;
        #pragma unroll
        for (int i = 0; i < 4; i++) {
            pml[tq * 4 + i]      = m[i];
            pml[N2 + tq * 4 + i] = l[i];
        }
    }
}

// ---------------------------------------------------------------------------
// Merge partials -> g_attnh (half)
// ---------------------------------------------------------------------------
__global__ __launch_bounds__(256) void attn_merge()
{
    const int bh = blockIdx.x;
    const int b = bh / HEADS;
    const int h = bh - b * HEADS;
    const int tid = threadIdx.x;
    const int q  = tid >> 2;
    const int dq = tid & 3;

    float ms[NSPLIT], ls[NSPLIT];
    float M = -1e30f;
    #pragma unroll
    for (int s = 0; s < NSPLIT; s++) {
        const float* pml = g_pml + (size_t)(bh * NSPLIT + s) * 2 * N2;
        ms[s] = pml[q];
        ls[s] = pml[N2 + q];
        M = fmaxf(M, ms[s]);
    }
    float w[NSPLIT], lt = 0.f;
    #pragma unroll
    for (int s = 0; s < NSPLIT; s++) {
        w[s] = __expf(ms[s] - M);
        lt += ls[s] * w[s];
    }
    const float inv = 1.0f / lt;

    __half* dst = g_attnh + ((size_t)(b * N2 + q)) * DIM + h * DH + dq * 16;
    #pragma unroll
    for (int j = 0; j < 4; j++) {
        float4 acc = make_float4(0.f, 0.f, 0.f, 0.f);
        #pragma unroll
        for (int s = 0; s < NSPLIT; s++) {
            const float4 v = *reinterpret_cast<const float4*>(
                g_pO + ((size_t)(bh * NSPLIT + s) * N2 + q) * DH + dq * 16 + j * 4);
            acc.x += w[s] * v.x;
            acc.y += w[s] * v.y;
            acc.z += w[s] * v.z;
            acc.w += w[s] * v.w;
        }
        __half2 h0 = make_half2(__float2half_rn(acc.x * inv), __float2half_rn(acc.y * inv));
        __half2 h1 = make_half2(__float2half_rn(acc.z * inv), __float2half_rn(acc.w * inv));
        *reinterpret_cast<__half2*>(dst + j * 4)     = h0;
        *reinterpret_cast<__half2*>(dst + j * 4 + 2) = h1;
    }
}

// ---------------------------------------------------------------------------
// Launch
// ---------------------------------------------------------------------------
extern "C" void kernel_launch(void* const* d_in, const int* in_sizes, int n_in,
                              void* d_out, int out_size)
{
    const float* x       = (const float*)d_in[0];
    const float* latents = (const float*)d_in[1];
    const float* mask    = (const float*)d_in[2];
    const float* ln1g    = (const float*)d_in[3];
    const float* ln1b    = (const float*)d_in[4];
    const float* ln2g    = (const float*)d_in[5];
    const float* ln2b    = (const float*)d_in[6];
    const float* Wq      = (const float*)d_in[7];
    const float* Wkv     = (const float*)d_in[8];
    const float* Wout    = (const float*)d_in[9];
    float* out = (float*)d_out;

    __half *p_kvin, *p_lnh, *p_kvh, *p_attnh, *p_wkvT, *p_wqT, *p_woT;
    float  *p_q;
    cudaGetSymbolAddress((void**)&p_kvin,  g_kvin);
    cudaGetSymbolAddress((void**)&p_lnh,   g_lnh);
    cudaGetSymbolAddress((void**)&p_q,     g_q);
    cudaGetSymbolAddress((void**)&p_kvh,   g_kvh);
    cudaGetSymbolAddress((void**)&p_attnh, g_attnh);
    cudaGetSymbolAddress((void**)&p_wkvT,  g_wkvT);
    cudaGetSymbolAddress((void**)&p_wqT,   g_wqT);
    cudaGetSymbolAddress((void**)&p_woT,   g_woT);

    static bool attr_set = false;
    if (!attr_set) {
        cudaFuncSetAttribute(gemm_tc<__half>, cudaFuncAttributeMaxDynamicSharedMemorySize,
                             GEMM_SMEM_BYTES);
        cudaFuncSetAttribute(gemm_tc<float>, cudaFuncAttributeMaxDynamicSharedMemorySize,
                             GEMM_SMEM_BYTES);
        attr_set = true;
    }

    // 0) Transpose + fp16-round weights
    transpose_kernel<<<dim3(2 * DIM / 32, DIM / 32), dim3(32, 8)>>>(Wkv, p_wkvT, 2 * DIM);
    transpose_kernel<<<dim3(DIM / 32, DIM / 32), dim3(32, 8)>>>(Wq, p_wqT, DIM);
    transpose_kernel<<<dim3(DIM / 32, DIM / 32), dim3(32, 8)>>>(Wout, p_woT, DIM);

    // 1) LayerNorms (half outputs)
    ln_kernel<<<MROWS, 256>>>(x, latents, ln1g, ln1b, ln2g, ln2b);

    // 2) KV GEMM (fp16 mma, half output)
    gemm_tc<__half><<<dim3(2 * DIM / 128, MROWS / 128), 256, GEMM_SMEM_BYTES>>>(
        p_kvin, p_wkvT, p_kvh, 2 * DIM);

    // 3) Q GEMM (fp16 mma, float output)
    gemm_tc<float><<<dim3(DIM / 128, BATCH * N2 / 128), 256, GEMM_SMEM_BYTES>>>(
        p_lnh, p_wqT, p_q, DIM);

    // 4) Attention: split-K partials + merge (half output)
    attn_partial<<<dim3(HEADS, BATCH, NSPLIT), 256>>>(mask);
    attn_merge<<<BATCH * HEADS, 256>>>();

    // 5) Out GEMM (fp16 mma, float output) -> d_out
    gemm_tc<float><<<dim3(DIM / 128, BATCH * N2 / 128), 256, GEMM_SMEM_BYTES>>>(
        p_attnh, p_woT, out, DIM);
}

// round 8
// speedup vs baseline: 1.1424x; 1.1424x over previous
#include <cuda_runtime.h>
#include <cuda_fp16.h>
#include <cstdint>

// ---------------------------------------------------------------------------
// PerceiverAttention, sm_103 — Round 7:
//   * gemm_tc reverted to Round-5 config (256,2 + 3-stage) — R6 regressed
//   * NEW gemm_tc_s (64x64 tiles) for Q/Out GEMMs: 128 CTAs instead of 32
// ---------------------------------------------------------------------------

#define BATCH 8
#define N1 4096
#define N2 64
#define NKEYS 4160
#define DIM 1024
#define HEADS 16
#define DH 64
#define MROWS (BATCH * NKEYS)   // 33280
#define NSPLIT 5
#define CH_PER_SPLIT 13

__device__ __half g_kvin[(size_t)MROWS * DIM];
__device__ __half g_lnh [(size_t)BATCH * N2 * DIM];
__device__ float  g_q   [(size_t)BATCH * N2 * DIM];
__device__ __half g_kvh [(size_t)MROWS * 2 * DIM];
__device__ __half g_attnh[(size_t)BATCH * N2 * DIM];
__device__ __half g_wkvT[(size_t)2 * DIM * DIM];
__device__ __half g_wqT [(size_t)DIM * DIM];
__device__ __half g_woT [(size_t)DIM * DIM];
__device__ float  g_pO  [(size_t)BATCH * HEADS * NSPLIT * N2 * DH];
__device__ float  g_pml [(size_t)BATCH * HEADS * NSPLIT * 2 * N2];

// ---------------------------------------------------------------------------
// Helpers
// ---------------------------------------------------------------------------
__device__ __forceinline__ uint32_t smem_u32(const void* p) {
    uint32_t a;
    asm("{ .reg .u64 t; cvta.to.shared.u64 t, %1; cvt.u32.u64 %0, t; }" : "=r"(a) : "l"(p));
    return a;
}
__device__ __forceinline__ void cp_async16(uint32_t dst, const void* src) {
    asm volatile("cp.async.cg.shared.global [%0], [%1], 16;" :: "r"(dst), "l"(src));
}
__device__ __forceinline__ void cp_commit() {
    asm volatile("cp.async.commit_group;" ::: "memory");
}
template <int N>
__device__ __forceinline__ void cp_wait() {
    asm volatile("cp.async.wait_group %0;" :: "n"(N) : "memory");
}
__device__ __forceinline__ void mma_f16(float* d, const uint32_t* a, const uint32_t* b) {
    asm volatile(
        "mma.sync.aligned.m16n8k16.row.col.f32.f16.f16.f32 "
        "{%0,%1,%2,%3}, {%4,%5,%6,%7}, {%8,%9}, {%0,%1,%2,%3};"
        : "+f"(d[0]), "+f"(d[1]), "+f"(d[2]), "+f"(d[3])
        : "r"(a[0]), "r"(a[1]), "r"(a[2]), "r"(a[3]), "r"(b[0]), "r"(b[1]));
}
__device__ __forceinline__ void ldm_x4(uint32_t* r, uint32_t addr) {
    asm volatile("ldmatrix.sync.aligned.m8n8.x4.shared.b16 {%0,%1,%2,%3}, [%4];"
        : "=r"(r[0]), "=r"(r[1]), "=r"(r[2]), "=r"(r[3]) : "r"(addr));
}
__device__ __forceinline__ void store_pair(float* p, float a, float b) {
    *reinterpret_cast<float2*>(p) = make_float2(a, b);
}
__device__ __forceinline__ void store_pair(__half* p, float a, float b) {
    *reinterpret_cast<__half2*>(p) = make_half2(__float2half_rn(a), __float2half_rn(b));
}

// ---------------------------------------------------------------------------
// Weight transpose + fp16 round
// ---------------------------------------------------------------------------
__global__ __launch_bounds__(256) void transpose_kernel(
    const float* __restrict__ in, __half* __restrict__ out, int ncols)
{
    __shared__ float t[32][33];
    const int bx = blockIdx.x * 32;
    const int by = blockIdx.y * 32;
    const int x = threadIdx.x;
    const int y = threadIdx.y;
    #pragma unroll
    for (int i = 0; i < 32; i += 8)
        t[y + i][x] = in[(size_t)(by + y + i) * ncols + bx + x];
    __syncthreads();
    #pragma unroll
    for (int i = 0; i < 32; i += 8)
        out[(size_t)(bx + y + i) * DIM + by + x] = __float2half_rn(t[x][y + i]);
}

// ---------------------------------------------------------------------------
// LayerNorm -> half outputs
// ---------------------------------------------------------------------------
__global__ __launch_bounds__(256) void ln_kernel(
    const float* __restrict__ x, const float* __restrict__ lat,
    const float* __restrict__ g1, const float* __restrict__ b1,
    const float* __restrict__ g2, const float* __restrict__ b2)
{
    __shared__ float red[16];
    const int r  = blockIdx.x;
    const int bb = r / NKEYS;
    const int i  = r - bb * NKEYS;

    const float* src;
    const float* g;
    const float* be;
    __half* dst2 = nullptr;
    if (i < N1) {
        src = x + ((size_t)bb * N1 + i) * DIM;
        g = g1; be = b1;
    } else {
        const int j = i - N1;
        src = lat + ((size_t)bb * N2 + j) * DIM;
        g = g2; be = b2;
        dst2 = g_lnh + ((size_t)bb * N2 + j) * DIM;
    }
    __half* dst = g_kvin + (size_t)r * DIM;

    const int t = threadIdx.x;
    float4 v = reinterpret_cast<const float4*>(src)[t];
    float s  = v.x + v.y + v.z + v.w;
    float sq = v.x * v.x + v.y * v.y + v.z * v.z + v.w * v.w;
    #pragma unroll
    for (int o = 16; o > 0; o >>= 1) {
        s  += __shfl_xor_sync(0xffffffffu, s, o);
        sq += __shfl_xor_sync(0xffffffffu, sq, o);
    }
    if ((t & 31) == 0) { red[t >> 5] = s; red[8 + (t >> 5)] = sq; }
    __syncthreads();
    float S = 0.f, SQ = 0.f;
    #pragma unroll
    for (int k = 0; k < 8; k++) { S += red[k]; SQ += red[8 + k]; }

    const float mu   = S * (1.0f / DIM);
    const float var  = SQ * (1.0f / DIM) - mu * mu;
    const float rstd = rsqrtf(var + 1e-5f);

    float4 gv = reinterpret_cast<const float4*>(g)[t];
    float4 bv = reinterpret_cast<const float4*>(be)[t];
    __half2 h0 = make_half2(__float2half_rn((v.x - mu) * rstd * gv.x + bv.x),
                            __float2half_rn((v.y - mu) * rstd * gv.y + bv.y));
    __half2 h1 = make_half2(__float2half_rn((v.z - mu) * rstd * gv.z + bv.z),
                            __float2half_rn((v.w - mu) * rstd * gv.w + bv.w));
    reinterpret_cast<__half2*>(dst)[t * 2]     = h0;
    reinterpret_cast<__half2*>(dst)[t * 2 + 1] = h1;
    if (dst2) {
        reinterpret_cast<__half2*>(dst2)[t * 2]     = h0;
        reinterpret_cast<__half2*>(dst2)[t * 2 + 1] = h1;
    }
}

// ---------------------------------------------------------------------------
// fp16 mma.sync GEMM (128x128 tile) — Round-5 configuration
// ---------------------------------------------------------------------------
#define PADH 72
#define TILE_H (128 * PADH)
#define NSTAGE 3
#define GEMM_SMEM_BYTES (NSTAGE * 2 * TILE_H * 2)   // 110592

template <typename OutT>
__global__ __launch_bounds__(256, 2) void gemm_tc(
    const __half* __restrict__ A, const __half* __restrict__ Bt,
    OutT* __restrict__ C, int ldc)
{
    extern __shared__ __half smh[];
    const uint32_t sb = smem_u32(smh);

    const int tid  = threadIdx.x;
    const int wid  = tid >> 5;
    const int lane = tid & 31;
    const int wm = wid & 3;
    const int wn = wid >> 2;
    const int m0 = blockIdx.y * 128;
    const int n0 = blockIdx.x * 128;

    const __half* ga = A  + (size_t)m0 * DIM;
    const __half* gb = Bt + (size_t)n0 * DIM;

    const int lr = tid >> 3;
    const int lc = tid & 7;

    float acc[2][8][4];
    #pragma unroll
    for (int i = 0; i < 2; i++)
        #pragma unroll
        for (int j = 0; j < 8; j++)
            #pragma unroll
            for (int q = 0; q < 4; q++) acc[i][j][q] = 0.f;

    const uint32_t a_off = (uint32_t)(wm * 32 + (lane & 15)) * PADH + (lane >> 4) * 8;
    const uint32_t b_off = (uint32_t)(wn * 64 + ((lane >> 4) << 3) + (lane & 7)) * PADH
                         + ((lane >> 3) & 1) * 8;

    auto load_tile = [&](int chunk, int stage) {
        const uint32_t abase = sb + (uint32_t)stage * 2 * TILE_H * 2;
        const uint32_t bbase = abase + TILE_H * 2;
        const int k0 = chunk * 64;
        #pragma unroll
        for (int i = 0; i < 4; i++) {
            const int r = lr + i * 32;
            cp_async16(abase + (r * PADH + lc * 8) * 2, ga + (size_t)r * DIM + k0 + lc * 8);
        }
        #pragma unroll
        for (int i = 0; i < 4; i++) {
            const int r = lr + i * 32;
            cp_async16(bbase + (r * PADH + lc * 8) * 2, gb + (size_t)r * DIM + k0 + lc * 8);
        }
        cp_commit();
    };

    const int NCHUNK = DIM / 64;   // 16
    load_tile(0, 0);
    load_tile(1, 1);

    for (int c = 0; c < NCHUNK; c++) {
        const int stage = c % NSTAGE;
        if (c + 2 < NCHUNK) { load_tile(c + 2, (c + 2) % NSTAGE); cp_wait<1>(); }
        else                { cp_wait<0>(); }
        __syncthreads();

        const uint32_t sA = sb + (uint32_t)stage * 2 * TILE_H * 2;
        const uint32_t sB = sA + TILE_H * 2;

        #pragma unroll
        for (int kk = 0; kk < 4; kk++) {
            uint32_t af[2][4], bf[8][2];
            #pragma unroll
            for (int mt = 0; mt < 2; mt++)
                ldm_x4(af[mt], sA + (a_off + (uint32_t)(mt * 16) * PADH + kk * 16) * 2);
            #pragma unroll
            for (int p = 0; p < 4; p++) {
                uint32_t r4[4];
                ldm_x4(r4, sB + (b_off + (uint32_t)(p * 16) * PADH + kk * 16) * 2);
                bf[2 * p][0]     = r4[0];
                bf[2 * p][1]     = r4[1];
                bf[2 * p + 1][0] = r4[2];
                bf[2 * p + 1][1] = r4[3];
            }
            #pragma unroll
            for (int mt = 0; mt < 2; mt++)
                #pragma unroll
                for (int nt = 0; nt < 8; nt++)
                    mma_f16(acc[mt][nt], af[mt], bf[nt]);
        }
        __syncthreads();
    }

    #pragma unroll
    for (int mt = 0; mt < 2; mt++) {
        const int row = m0 + wm * 32 + mt * 16 + (lane >> 2);
        #pragma unroll
        for (int nt = 0; nt < 8; nt++) {
            const int col = n0 + wn * 64 + nt * 8 + (lane & 3) * 2;
            store_pair(C + (size_t)row * ldc + col, acc[mt][nt][0], acc[mt][nt][1]);
            store_pair(C + (size_t)(row + 8) * ldc + col, acc[mt][nt][2], acc[mt][nt][3]);
        }
    }
}

// ---------------------------------------------------------------------------
// Small-tile fp16 GEMM (64x64 CTA tile, 8 warps, warp tile 16x32) for the
// 512-row Q/Out GEMMs: grid = (N/64, M/64) = 128 CTAs.
// ---------------------------------------------------------------------------
#define TILE_HS (64 * PADH)
#define GEMM_S_SMEM_BYTES (NSTAGE * 2 * TILE_HS * 2)   // 55296

template <typename OutT>
__global__ __launch_bounds__(256, 2) void gemm_tc_s(
    const __half* __restrict__ A, const __half* __restrict__ Bt,
    OutT* __restrict__ C, int ldc)
{
    extern __shared__ __half smh[];
    const uint32_t sb = smem_u32(smh);

    const int tid  = threadIdx.x;
    const int wid  = tid >> 5;
    const int lane = tid & 31;
    const int wm = wid & 3;        // 4 m16 groups
    const int wn = wid >> 2;       // 2 n32 groups
    const int m0 = blockIdx.y * 64;
    const int n0 = blockIdx.x * 64;

    const __half* ga = A  + (size_t)m0 * DIM;
    const __half* gb = Bt + (size_t)n0 * DIM;

    const int lr = tid >> 3;       // 0..31
    const int lc = tid & 7;

    float acc[4][4];
    #pragma unroll
    for (int j = 0; j < 4; j++)
        #pragma unroll
        for (int q = 0; q < 4; q++) acc[j][q] = 0.f;

    const uint32_t a_off = (uint32_t)(wm * 16 + (lane & 15)) * PADH + (lane >> 4) * 8;
    const uint32_t b_off = (uint32_t)(wn * 32 + ((lane >> 4) << 3) + (lane & 7)) * PADH
                         + ((lane >> 3) & 1) * 8;

    auto load_tile = [&](int chunk, int stage) {
        const uint32_t abase = sb + (uint32_t)stage * 2 * TILE_HS * 2;
        const uint32_t bbase = abase + TILE_HS * 2;
        const int k0 = chunk * 64;
        #pragma unroll
        for (int i = 0; i < 2; i++) {
            const int r = lr + i * 32;
            cp_async16(abase + (r * PADH + lc * 8) * 2, ga + (size_t)r * DIM + k0 + lc * 8);
        }
        #pragma unroll
        for (int i = 0; i < 2; i++) {
            const int r = lr + i * 32;
            cp_async16(bbase + (r * PADH + lc * 8) * 2, gb + (size_t)r * DIM + k0 + lc * 8);
        }
        cp_commit();
    };

    const int NCHUNK = DIM / 64;   // 16
    load_tile(0, 0);
    load_tile(1, 1);

    for (int c = 0; c < NCHUNK; c++) {
        const int stage = c % NSTAGE;
        if (c + 2 < NCHUNK) { load_tile(c + 2, (c + 2) % NSTAGE); cp_wait<1>(); }
        else                { cp_wait<0>(); }
        __syncthreads();

        const uint32_t sA = sb + (uint32_t)stage * 2 * TILE_HS * 2;
        const uint32_t sB = sA + TILE_HS * 2;

        #pragma unroll
        for (int kk = 0; kk < 4; kk++) {
            uint32_t af[4], bf[4][2];
            ldm_x4(af, sA + (a_off + kk * 16) * 2);
            #pragma unroll
            for (int p = 0; p < 2; p++) {
                uint32_t r4[4];
                ldm_x4(r4, sB + (b_off + (uint32_t)(p * 16) * PADH + kk * 16) * 2);
                bf[2 * p][0]     = r4[0];
                bf[2 * p][1]     = r4[1];
                bf[2 * p + 1][0] = r4[2];
                bf[2 * p + 1][1] = r4[3];
            }
            #pragma unroll
            for (int nt = 0; nt < 4; nt++)
                mma_f16(acc[nt], af, bf[nt]);
        }
        __syncthreads();
    }

    const int row = m0 + wm * 16 + (lane >> 2);
    #pragma unroll
    for (int nt = 0; nt < 4; nt++) {
        const int col = n0 + wn * 32 + nt * 8 + (lane & 3) * 2;
        store_pair(C + (size_t)row * ldc + col, acc[nt][0], acc[nt][1]);
        store_pair(C + (size_t)(row + 8) * ldc + col, acc[nt][2], acc[nt][3]);
    }
}

// ---------------------------------------------------------------------------
// Split-K flash attention (fp32 compute; KV loaded as half)
// ---------------------------------------------------------------------------
__global__ __launch_bounds__(256) void attn_partial(const float* __restrict__ mask)
{
    __shared__ float qs_t[64 * 64];
    __shared__ float ks_t[64 * 64];
    __shared__ float vs  [64 * 64];

    const int h = blockIdx.x;
    const int b = blockIdx.y;
    const int sp = blockIdx.z;
    const int bh = b * HEADS + h;
    const int tid = threadIdx.x;
    const int tq = tid >> 4;
    const int tx = tid & 15;

    {
        const int qr = tid >> 2;
        const int dg = tid & 3;
        const float4* src = reinterpret_cast<const float4*>(
            g_q + ((size_t)(b * N2 + qr)) * DIM + h * DH + dg * 16);
        #pragma unroll
        for (int ii = 0; ii < 4; ii++) {
            float4 v = src[ii];
            const int d0 = dg * 16 + ii * 4;
            qs_t[(d0 + 0) * 64 + qr] = v.x * 0.125f;
            qs_t[(d0 + 1) * 64 + qr] = v.y * 0.125f;
            qs_t[(d0 + 2) * 64 + qr] = v.z * 0.125f;
            qs_t[(d0 + 3) * 64 + qr] = v.w * 0.125f;
        }
    }

    float O[4][4] = {};
    float m[4], l[4];
    #pragma unroll
    for (int i = 0; i < 4; i++) { m[i] = -1e30f; l[i] = 0.f; }

    const size_t kvbase = (size_t)b * NKEYS * (2 * DIM);

    for (int cc = 0; cc < CH_PER_SPLIT; cc++) {
        const int key0 = (sp * CH_PER_SPLIT + cc) * 64;
        __syncthreads();

        {
            const int kl = tid >> 2;
            const int dg = tid & 3;
            const uint4* ksrc = reinterpret_cast<const uint4*>(
                g_kvh + kvbase + (size_t)(key0 + kl) * (2 * DIM) + h * DH + dg * 16);
            #pragma unroll
            for (int part = 0; part < 2; part++) {
                uint4 u = ksrc[part];
                const __half2* hp = reinterpret_cast<const __half2*>(&u);
                const int d0 = dg * 16 + part * 8;
                #pragma unroll
                for (int j = 0; j < 4; j++) {
                    float2 f = __half22float2(hp[j]);
                    ks_t[(d0 + 2 * j) * 64 + kl]     = f.x;
                    ks_t[(d0 + 2 * j + 1) * 64 + kl] = f.y;
                }
            }
            const uint4* vsrc = reinterpret_cast<const uint4*>(
                g_kvh + kvbase + (size_t)(key0 + kl) * (2 * DIM) + DIM + h * DH + dg * 16);
            #pragma unroll
            for (int part = 0; part < 2; part++) {
                uint4 u = vsrc[part];
                const __half2* hp = reinterpret_cast<const __half2*>(&u);
                const int d0 = dg * 16 + part * 8;
                #pragma unroll
                for (int j = 0; j < 4; j++) {
                    float2 f = __half22float2(hp[j]);
                    vs[kl * 64 + d0 + 2 * j]     = f.x;
                    vs[kl * 64 + d0 + 2 * j + 1] = f.y;
                }
            }
        }
        __syncthreads();

        float acc[4][4] = {};
        #pragma unroll 8
        for (int d = 0; d < 64; d++) {
            float4 av = *reinterpret_cast<const float4*>(qs_t + d * 64 + tq * 4);
            float4 bv = *reinterpret_cast<const float4*>(ks_t + d * 64 + tx * 4);
            float a[4] = {av.x, av.y, av.z, av.w};
            float kb[4] = {bv.x, bv.y, bv.z, bv.w};
            #pragma unroll
            for (int i = 0; i < 4; i++)
                #pragma unroll
                for (int j = 0; j < 4; j++)
                    acc[i][j] += a[i] * kb[j];
        }

        #pragma unroll
        for (int j = 0; j < 4; j++) {
            const int kg = key0 + tx * 4 + j;
            float bias = 0.f;
            if (kg < N1) bias = (mask[(size_t)b * N1 + kg] - 1.0f) * 100.0f;
            #pragma unroll
            for (int i = 0; i < 4; i++) acc[i][j] += bias;
        }

        float alpha[4];
        #pragma unroll
        for (int i = 0; i < 4; i++) {
            float cm = fmaxf(fmaxf(acc[i][0], acc[i][1]), fmaxf(acc[i][2], acc[i][3]));
            #pragma unroll
            for (int o = 1; o < 16; o <<= 1)
                cm = fmaxf(cm, __shfl_xor_sync(0xffffffffu, cm, o));
            const float mn = fmaxf(m[i], cm);
            alpha[i] = __expf(m[i] - mn);
            float cl = 0.f;
            #pragma unroll
            for (int j = 0; j < 4; j++) {
                const float p = __expf(acc[i][j] - mn);
                acc[i][j] = p;
                cl += p;
            }
            #pragma unroll
            for (int o = 1; o < 16; o <<= 1)
                cl += __shfl_xor_sync(0xffffffffu, cl, o);
            l[i] = l[i] * alpha[i] + cl;
            m[i] = mn;
            #pragma unroll
            for (int j = 0; j < 4; j++) O[i][j] *= alpha[i];
        }

        __syncthreads();
        #pragma unroll
        for (int i = 0; i < 4; i++)
            #pragma unroll
            for (int j = 0; j < 4; j++)
                ks_t[(tq * 4 + i) * 64 + tx * 4 + j] = acc[i][j];
        __syncthreads();

        #pragma unroll 8
        for (int k = 0; k < 64; k++) {
            float p0 = ks_t[(tq * 4 + 0) * 64 + k];
            float p1 = ks_t[(tq * 4 + 1) * 64 + k];
            float p2 = ks_t[(tq * 4 + 2) * 64 + k];
            float p3 = ks_t[(tq * 4 + 3) * 64 + k];
            float4 vv = *reinterpret_cast<const float4*>(vs + k * 64 + tx * 4);
            float v4[4] = {vv.x, vv.y, vv.z, vv.w};
            #pragma unroll
            for (int j = 0; j < 4; j++) {
                O[0][j] += p0 * v4[j];
                O[1][j] += p1 * v4[j];
                O[2][j] += p2 * v4[j];
                O[3][j] += p3 * v4[j];
            }
        }
    }

    float* po = g_pO + ((size_t)(bh * NSPLIT + sp) * N2) * DH;
    #pragma unroll
    for (int i = 0; i < 4; i++) {
        *reinterpret_cast<float4*>(po + (size_t)(tq * 4 + i) * DH + tx * 4) =
            make_float4(O[i][0], O[i][1], O[i][2], O[i][3]);
    }
    if (tx == 0) {
        float* pml = g_pml + (size_t)(bh * NSPLIT + sp) * 2 * N2;
        #pragma unroll
        for (int i = 0; i < 4; i++) {
            pml[tq * 4 + i]      = m[i];
            pml[N2 + tq * 4 + i] = l[i];
        }
    }
}

// ---------------------------------------------------------------------------
// Merge partials -> g_attnh (half)
// ---------------------------------------------------------------------------
__global__ __launch_bounds__(256) void attn_merge()
{
    const int bh = blockIdx.x;
    const int b = bh / HEADS;
    const int h = bh - b * HEADS;
    const int tid = threadIdx.x;
    const int q  = tid >> 2;
    const int dq = tid & 3;

    float ms[NSPLIT], ls[NSPLIT];
    float M = -1e30f;
    #pragma unroll
    for (int s = 0; s < NSPLIT; s++) {
        const float* pml = g_pml + (size_t)(bh * NSPLIT + s) * 2 * N2;
        ms[s] = pml[q];
        ls[s] = pml[N2 + q];
        M = fmaxf(M, ms[s]);
    }
    float w[NSPLIT], lt = 0.f;
    #pragma unroll
    for (int s = 0; s < NSPLIT; s++) {
        w[s] = __expf(ms[s] - M);
        lt += ls[s] * w[s];
    }
    const float inv = 1.0f / lt;

    __half* dst = g_attnh + ((size_t)(b * N2 + q)) * DIM + h * DH + dq * 16;
    #pragma unroll
    for (int j = 0; j < 4; j++) {
        float4 acc = make_float4(0.f, 0.f, 0.f, 0.f);
        #pragma unroll
        for (int s = 0; s < NSPLIT; s++) {
            const float4 v = *reinterpret_cast<const float4*>(
                g_pO + ((size_t)(bh * NSPLIT + s) * N2 + q) * DH + dq * 16 + j * 4);
            acc.x += w[s] * v.x;
            acc.y += w[s] * v.y;
            acc.z += w[s] * v.z;
            acc.w += w[s] * v.w;
        }
        __half2 h0 = make_half2(__float2half_rn(acc.x * inv), __float2half_rn(acc.y * inv));
        __half2 h1 = make_half2(__float2half_rn(acc.z * inv), __float2half_rn(acc.w * inv));
        *reinterpret_cast<__half2*>(dst + j * 4)     = h0;
        *reinterpret_cast<__half2*>(dst + j * 4 + 2) = h1;
    }
}

// ---------------------------------------------------------------------------
// Launch
// ---------------------------------------------------------------------------
extern "C" void kernel_launch(void* const* d_in, const int* in_sizes, int n_in,
                              void* d_out, int out_size)
{
    const float* x       = (const float*)d_in[0];
    const float* latents = (const float*)d_in[1];
    const float* mask    = (const float*)d_in[2];
    const float* ln1g    = (const float*)d_in[3];
    const float* ln1b    = (const float*)d_in[4];
    const float* ln2g    = (const float*)d_in[5];
    const float* ln2b    = (const float*)d_in[6];
    const float* Wq      = (const float*)d_in[7];
    const float* Wkv     = (const float*)d_in[8];
    const float* Wout    = (const float*)d_in[9];
    float* out = (float*)d_out;

    __half *p_kvin, *p_lnh, *p_kvh, *p_attnh, *p_wkvT, *p_wqT, *p_woT;
    float  *p_q;
    cudaGetSymbolAddress((void**)&p_kvin,  g_kvin);
    cudaGetSymbolAddress((void**)&p_lnh,   g_lnh);
    cudaGetSymbolAddress((void**)&p_q,     g_q);
    cudaGetSymbolAddress((void**)&p_kvh,   g_kvh);
    cudaGetSymbolAddress((void**)&p_attnh, g_attnh);
    cudaGetSymbolAddress((void**)&p_wkvT,  g_wkvT);
    cudaGetSymbolAddress((void**)&p_wqT,   g_wqT);
    cudaGetSymbolAddress((void**)&p_woT,   g_woT);

    static bool attr_set = false;
    if (!attr_set) {
        cudaFuncSetAttribute(gemm_tc<__half>, cudaFuncAttributeMaxDynamicSharedMemorySize,
                             GEMM_SMEM_BYTES);
        cudaFuncSetAttribute(gemm_tc<float>, cudaFuncAttributeMaxDynamicSharedMemorySize,
                             GEMM_SMEM_BYTES);
        cudaFuncSetAttribute(gemm_tc_s<float>, cudaFuncAttributeMaxDynamicSharedMemorySize,
                             GEMM_S_SMEM_BYTES);
        attr_set = true;
    }

    // 0) Transpose + fp16-round weights
    transpose_kernel<<<dim3(2 * DIM / 32, DIM / 32), dim3(32, 8)>>>(Wkv, p_wkvT, 2 * DIM);
    transpose_kernel<<<dim3(DIM / 32, DIM / 32), dim3(32, 8)>>>(Wq, p_wqT, DIM);
    transpose_kernel<<<dim3(DIM / 32, DIM / 32), dim3(32, 8)>>>(Wout, p_woT, DIM);

    // 1) LayerNorms (half outputs)
    ln_kernel<<<MROWS, 256>>>(x, latents, ln1g, ln1b, ln2g, ln2b);

    // 2) KV GEMM (fp16 mma, half output)
    gemm_tc<__half><<<dim3(2 * DIM / 128, MROWS / 128), 256, GEMM_SMEM_BYTES>>>(
        p_kvin, p_wkvT, p_kvh, 2 * DIM);

    // 3) Q GEMM (small tiles: 128 CTAs)
    gemm_tc_s<float><<<dim3(DIM / 64, BATCH * N2 / 64), 256, GEMM_S_SMEM_BYTES>>>(
        p_lnh, p_wqT, p_q, DIM);

    // 4) Attention: split-K partials + merge (half output)
    attn_partial<<<dim3(HEADS, BATCH, NSPLIT), 256>>>(mask);
    attn_merge<<<BATCH * HEADS, 256>>>();

    // 5) Out GEMM (small tiles) -> d_out
    gemm_tc_s<float><<<dim3(DIM / 64, BATCH * N2 / 64), 256, GEMM_S_SMEM_BYTES>>>(
        p_attnh, p_woT, out, DIM);
}

// round 9
// speedup vs baseline: 1.5852x; 1.3875x over previous
#include <cuda_runtime.h>
#include <cuda_fp16.h>
#include <cstdint>

// ---------------------------------------------------------------------------
// PerceiverAttention, sm_103 — Round 8:
//   * attn_partial rewritten on fp16 mma.sync (m16n8k16):
//       - K used in natural [key][dh] layout (no transpose)
//       - softmax in registers (quad shuffles), mask bias via smem
//       - P reused register-to-register as next MMA's A fragment
//       - V scalar-transposed to [dh][key] at load
//   * Q GEMM emits __half (g_qh)
// ---------------------------------------------------------------------------

#define BATCH 8
#define N1 4096
#define N2 64
#define NKEYS 4160
#define DIM 1024
#define HEADS 16
#define DH 64
#define MROWS (BATCH * NKEYS)   // 33280
#define NSPLIT 5
#define CH_PER_SPLIT 13

__device__ __half g_kvin[(size_t)MROWS * DIM];
__device__ __half g_lnh [(size_t)BATCH * N2 * DIM];
__device__ __half g_qh  [(size_t)BATCH * N2 * DIM];
__device__ __half g_kvh [(size_t)MROWS * 2 * DIM];
__device__ __half g_attnh[(size_t)BATCH * N2 * DIM];
__device__ __half g_wkvT[(size_t)2 * DIM * DIM];
__device__ __half g_wqT [(size_t)DIM * DIM];
__device__ __half g_woT [(size_t)DIM * DIM];
__device__ float  g_pO  [(size_t)BATCH * HEADS * NSPLIT * N2 * DH];
__device__ float  g_pml [(size_t)BATCH * HEADS * NSPLIT * 2 * N2];

// ---------------------------------------------------------------------------
// Helpers
// ---------------------------------------------------------------------------
__device__ __forceinline__ uint32_t smem_u32(const void* p) {
    uint32_t a;
    asm("{ .reg .u64 t; cvta.to.shared.u64 t, %1; cvt.u32.u64 %0, t; }" : "=r"(a) : "l"(p));
    return a;
}
__device__ __forceinline__ void cp_async16(uint32_t dst, const void* src) {
    asm volatile("cp.async.cg.shared.global [%0], [%1], 16;" :: "r"(dst), "l"(src));
}
__device__ __forceinline__ void cp_commit() {
    asm volatile("cp.async.commit_group;" ::: "memory");
}
template <int N>
__device__ __forceinline__ void cp_wait() {
    asm volatile("cp.async.wait_group %0;" :: "n"(N) : "memory");
}
__device__ __forceinline__ void mma_f16(float* d, const uint32_t* a, const uint32_t* b) {
    asm volatile(
        "mma.sync.aligned.m16n8k16.row.col.f32.f16.f16.f32 "
        "{%0,%1,%2,%3}, {%4,%5,%6,%7}, {%8,%9}, {%0,%1,%2,%3};"
        : "+f"(d[0]), "+f"(d[1]), "+f"(d[2]), "+f"(d[3])
        : "r"(a[0]), "r"(a[1]), "r"(a[2]), "r"(a[3]), "r"(b[0]), "r"(b[1]));
}
__device__ __forceinline__ void ldm_x4(uint32_t* r, uint32_t addr) {
    asm volatile("ldmatrix.sync.aligned.m8n8.x4.shared.b16 {%0,%1,%2,%3}, [%4];"
        : "=r"(r[0]), "=r"(r[1]), "=r"(r[2]), "=r"(r[3]) : "r"(addr));
}
__device__ __forceinline__ uint32_t pack_h2(float a, float b) {
    __half2 h = __floats2half2_rn(a, b);
    return *reinterpret_cast<uint32_t*>(&h);
}
__device__ __forceinline__ void store_pair(float* p, float a, float b) {
    *reinterpret_cast<float2*>(p) = make_float2(a, b);
}
__device__ __forceinline__ void store_pair(__half* p, float a, float b) {
    *reinterpret_cast<__half2*>(p) = make_half2(__float2half_rn(a), __float2half_rn(b));
}

// ---------------------------------------------------------------------------
// Weight transpose + fp16 round
// ---------------------------------------------------------------------------
__global__ __launch_bounds__(256) void transpose_kernel(
    const float* __restrict__ in, __half* __restrict__ out, int ncols)
{
    __shared__ float t[32][33];
    const int bx = blockIdx.x * 32;
    const int by = blockIdx.y * 32;
    const int x = threadIdx.x;
    const int y = threadIdx.y;
    #pragma unroll
    for (int i = 0; i < 32; i += 8)
        t[y + i][x] = in[(size_t)(by + y + i) * ncols + bx + x];
    __syncthreads();
    #pragma unroll
    for (int i = 0; i < 32; i += 8)
        out[(size_t)(bx + y + i) * DIM + by + x] = __float2half_rn(t[x][y + i]);
}

// ---------------------------------------------------------------------------
// LayerNorm -> half outputs
// ---------------------------------------------------------------------------
__global__ __launch_bounds__(256) void ln_kernel(
    const float* __restrict__ x, const float* __restrict__ lat,
    const float* __restrict__ g1, const float* __restrict__ b1,
    const float* __restrict__ g2, const float* __restrict__ b2)
{
    __shared__ float red[16];
    const int r  = blockIdx.x;
    const int bb = r / NKEYS;
    const int i  = r - bb * NKEYS;

    const float* src;
    const float* g;
    const float* be;
    __half* dst2 = nullptr;
    if (i < N1) {
        src = x + ((size_t)bb * N1 + i) * DIM;
        g = g1; be = b1;
    } else {
        const int j = i - N1;
        src = lat + ((size_t)bb * N2 + j) * DIM;
        g = g2; be = b2;
        dst2 = g_lnh + ((size_t)bb * N2 + j) * DIM;
    }
    __half* dst = g_kvin + (size_t)r * DIM;

    const int t = threadIdx.x;
    float4 v = reinterpret_cast<const float4*>(src)[t];
    float s  = v.x + v.y + v.z + v.w;
    float sq = v.x * v.x + v.y * v.y + v.z * v.z + v.w * v.w;
    #pragma unroll
    for (int o = 16; o > 0; o >>= 1) {
        s  += __shfl_xor_sync(0xffffffffu, s, o);
        sq += __shfl_xor_sync(0xffffffffu, sq, o);
    }
    if ((t & 31) == 0) { red[t >> 5] = s; red[8 + (t >> 5)] = sq; }
    __syncthreads();
    float S = 0.f, SQ = 0.f;
    #pragma unroll
    for (int k = 0; k < 8; k++) { S += red[k]; SQ += red[8 + k]; }

    const float mu   = S * (1.0f / DIM);
    const float var  = SQ * (1.0f / DIM) - mu * mu;
    const float rstd = rsqrtf(var + 1e-5f);

    float4 gv = reinterpret_cast<const float4*>(g)[t];
    float4 bv = reinterpret_cast<const float4*>(be)[t];
    __half2 h0 = make_half2(__float2half_rn((v.x - mu) * rstd * gv.x + bv.x),
                            __float2half_rn((v.y - mu) * rstd * gv.y + bv.y));
    __half2 h1 = make_half2(__float2half_rn((v.z - mu) * rstd * gv.z + bv.z),
                            __float2half_rn((v.w - mu) * rstd * gv.w + bv.w));
    reinterpret_cast<__half2*>(dst)[t * 2]     = h0;
    reinterpret_cast<__half2*>(dst)[t * 2 + 1] = h1;
    if (dst2) {
        reinterpret_cast<__half2*>(dst2)[t * 2]     = h0;
        reinterpret_cast<__half2*>(dst2)[t * 2 + 1] = h1;
    }
}

// ---------------------------------------------------------------------------
// fp16 mma.sync GEMM (128x128 tile)
// ---------------------------------------------------------------------------
#define PADH 72
#define TILE_H (128 * PADH)
#define NSTAGE 3
#define GEMM_SMEM_BYTES (NSTAGE * 2 * TILE_H * 2)   // 110592

template <typename OutT>
__global__ __launch_bounds__(256, 2) void gemm_tc(
    const __half* __restrict__ A, const __half* __restrict__ Bt,
    OutT* __restrict__ C, int ldc)
{
    extern __shared__ __half smh[];
    const uint32_t sb = smem_u32(smh);

    const int tid  = threadIdx.x;
    const int wid  = tid >> 5;
    const int lane = tid & 31;
    const int wm = wid & 3;
    const int wn = wid >> 2;
    const int m0 = blockIdx.y * 128;
    const int n0 = blockIdx.x * 128;

    const __half* ga = A  + (size_t)m0 * DIM;
    const __half* gb = Bt + (size_t)n0 * DIM;

    const int lr = tid >> 3;
    const int lc = tid & 7;

    float acc[2][8][4];
    #pragma unroll
    for (int i = 0; i < 2; i++)
        #pragma unroll
        for (int j = 0; j < 8; j++)
            #pragma unroll
            for (int q = 0; q < 4; q++) acc[i][j][q] = 0.f;

    const uint32_t a_off = (uint32_t)(wm * 32 + (lane & 15)) * PADH + (lane >> 4) * 8;
    const uint32_t b_off = (uint32_t)(wn * 64 + ((lane >> 4) << 3) + (lane & 7)) * PADH
                         + ((lane >> 3) & 1) * 8;

    auto load_tile = [&](int chunk, int stage) {
        const uint32_t abase = sb + (uint32_t)stage * 2 * TILE_H * 2;
        const uint32_t bbase = abase + TILE_H * 2;
        const int k0 = chunk * 64;
        #pragma unroll
        for (int i = 0; i < 4; i++) {
            const int r = lr + i * 32;
            cp_async16(abase + (r * PADH + lc * 8) * 2, ga + (size_t)r * DIM + k0 + lc * 8);
        }
        #pragma unroll
        for (int i = 0; i < 4; i++) {
            const int r = lr + i * 32;
            cp_async16(bbase + (r * PADH + lc * 8) * 2, gb + (size_t)r * DIM + k0 + lc * 8);
        }
        cp_commit();
    };

    const int NCHUNK = DIM / 64;   // 16
    load_tile(0, 0);
    load_tile(1, 1);

    for (int c = 0; c < NCHUNK; c++) {
        const int stage = c % NSTAGE;
        if (c + 2 < NCHUNK) { load_tile(c + 2, (c + 2) % NSTAGE); cp_wait<1>(); }
        else                { cp_wait<0>(); }
        __syncthreads();

        const uint32_t sA = sb + (uint32_t)stage * 2 * TILE_H * 2;
        const uint32_t sB = sA + TILE_H * 2;

        #pragma unroll
        for (int kk = 0; kk < 4; kk++) {
            uint32_t af[2][4], bf[8][2];
            #pragma unroll
            for (int mt = 0; mt < 2; mt++)
                ldm_x4(af[mt], sA + (a_off + (uint32_t)(mt * 16) * PADH + kk * 16) * 2);
            #pragma unroll
            for (int p = 0; p < 4; p++) {
                uint32_t r4[4];
                ldm_x4(r4, sB + (b_off + (uint32_t)(p * 16) * PADH + kk * 16) * 2);
                bf[2 * p][0]     = r4[0];
                bf[2 * p][1]     = r4[1];
                bf[2 * p + 1][0] = r4[2];
                bf[2 * p + 1][1] = r4[3];
            }
            #pragma unroll
            for (int mt = 0; mt < 2; mt++)
                #pragma unroll
                for (int nt = 0; nt < 8; nt++)
                    mma_f16(acc[mt][nt], af[mt], bf[nt]);
        }
        __syncthreads();
    }

    #pragma unroll
    for (int mt = 0; mt < 2; mt++) {
        const int row = m0 + wm * 32 + mt * 16 + (lane >> 2);
        #pragma unroll
        for (int nt = 0; nt < 8; nt++) {
            const int col = n0 + wn * 64 + nt * 8 + (lane & 3) * 2;
            store_pair(C + (size_t)row * ldc + col, acc[mt][nt][0], acc[mt][nt][1]);
            store_pair(C + (size_t)(row + 8) * ldc + col, acc[mt][nt][2], acc[mt][nt][3]);
        }
    }
}

// ---------------------------------------------------------------------------
// Small-tile fp16 GEMM (64x64 CTA tile) for 512-row GEMMs
// ---------------------------------------------------------------------------
#define TILE_HS (64 * PADH)
#define GEMM_S_SMEM_BYTES (NSTAGE * 2 * TILE_HS * 2)   // 55296

template <typename OutT>
__global__ __launch_bounds__(256, 2) void gemm_tc_s(
    const __half* __restrict__ A, const __half* __restrict__ Bt,
    OutT* __restrict__ C, int ldc)
{
    extern __shared__ __half smh[];
    const uint32_t sb = smem_u32(smh);

    const int tid  = threadIdx.x;
    const int wid  = tid >> 5;
    const int lane = tid & 31;
    const int wm = wid & 3;
    const int wn = wid >> 2;
    const int m0 = blockIdx.y * 64;
    const int n0 = blockIdx.x * 64;

    const __half* ga = A  + (size_t)m0 * DIM;
    const __half* gb = Bt + (size_t)n0 * DIM;

    const int lr = tid >> 3;
    const int lc = tid & 7;

    float acc[4][4];
    #pragma unroll
    for (int j = 0; j < 4; j++)
        #pragma unroll
        for (int q = 0; q < 4; q++) acc[j][q] = 0.f;

    const uint32_t a_off = (uint32_t)(wm * 16 + (lane & 15)) * PADH + (lane >> 4) * 8;
    const uint32_t b_off = (uint32_t)(wn * 32 + ((lane >> 4) << 3) + (lane & 7)) * PADH
                         + ((lane >> 3) & 1) * 8;

    auto load_tile = [&](int chunk, int stage) {
        const uint32_t abase = sb + (uint32_t)stage * 2 * TILE_HS * 2;
        const uint32_t bbase = abase + TILE_HS * 2;
        const int k0 = chunk * 64;
        #pragma unroll
        for (int i = 0; i < 2; i++) {
            const int r = lr + i * 32;
            cp_async16(abase + (r * PADH + lc * 8) * 2, ga + (size_t)r * DIM + k0 + lc * 8);
        }
        #pragma unroll
        for (int i = 0; i < 2; i++) {
            const int r = lr + i * 32;
            cp_async16(bbase + (r * PADH + lc * 8) * 2, gb + (size_t)r * DIM + k0 + lc * 8);
        }
        cp_commit();
    };

    const int NCHUNK = DIM / 64;
    load_tile(0, 0);
    load_tile(1, 1);

    for (int c = 0; c < NCHUNK; c++) {
        const int stage = c % NSTAGE;
        if (c + 2 < NCHUNK) { load_tile(c + 2, (c + 2) % NSTAGE); cp_wait<1>(); }
        else                { cp_wait<0>(); }
        __syncthreads();

        const uint32_t sA = sb + (uint32_t)stage * 2 * TILE_HS * 2;
        const uint32_t sB = sA + TILE_HS * 2;

        #pragma unroll
        for (int kk = 0; kk < 4; kk++) {
            uint32_t af[4], bf[4][2];
            ldm_x4(af, sA + (a_off + kk * 16) * 2);
            #pragma unroll
            for (int p = 0; p < 2; p++) {
                uint32_t r4[4];
                ldm_x4(r4, sB + (b_off + (uint32_t)(p * 16) * PADH + kk * 16) * 2);
                bf[2 * p][0]     = r4[0];
                bf[2 * p][1]     = r4[1];
                bf[2 * p + 1][0] = r4[2];
                bf[2 * p + 1][1] = r4[3];
            }
            #pragma unroll
            for (int nt = 0; nt < 4; nt++)
                mma_f16(acc[nt], af, bf[nt]);
        }
        __syncthreads();
    }

    const int row = m0 + wm * 16 + (lane >> 2);
    #pragma unroll
    for (int nt = 0; nt < 4; nt++) {
        const int col = n0 + wn * 32 + nt * 8 + (lane & 3) * 2;
        store_pair(C + (size_t)row * ldc + col, acc[nt][0], acc[nt][1]);
        store_pair(C + (size_t)(row + 8) * ldc + col, acc[nt][2], acc[nt][3]);
    }
}

// ---------------------------------------------------------------------------
// Split-K flash attention on fp16 mma.sync.
// Grid (HEADS, BATCH, NSPLIT), 128 threads (4 warps; warp = 16 query rows).
// ---------------------------------------------------------------------------
#define APAD 72

__global__ __launch_bounds__(128) void attn_partial(const float* __restrict__ mask)
{
    __shared__ __half qs [64 * APAD];   // [query][dh]
    __shared__ __half ks [64 * APAD];   // [key][dh]
    __shared__ __half vst[64 * APAD];   // [dh][key]
    __shared__ float bias[64];

    const int h = blockIdx.x;
    const int b = blockIdx.y;
    const int sp = blockIdx.z;
    const int bh = b * HEADS + h;
    const int tid = threadIdx.x;
    const int wid = tid >> 5;
    const int lane = tid & 31;
    const uint32_t sq = smem_u32(qs);
    const uint32_t sk = smem_u32(ks);
    const uint32_t sv = smem_u32(vst);

    // Load Q (x 0.125), row-major [query][dh]
    {
        const int q = tid >> 1;
        const int d0 = (tid & 1) * 32;
        const uint4* src = reinterpret_cast<const uint4*>(
            g_qh + (size_t)(b * N2 + q) * DIM + h * DH + d0);
        const __half2 s2 = __half2half2(__float2half(0.125f));
        #pragma unroll
        for (int i = 0; i < 4; i++) {
            uint4 u = src[i];
            __half2* hp = reinterpret_cast<__half2*>(&u);
            #pragma unroll
            for (int j = 0; j < 4; j++) hp[j] = __hmul2(hp[j], s2);
            *reinterpret_cast<uint4*>(qs + q * APAD + d0 + i * 8) = u;
        }
    }

    float o[8][4];
    #pragma unroll
    for (int j = 0; j < 8; j++)
        #pragma unroll
        for (int q = 0; q < 4; q++) o[j][q] = 0.f;
    float m0r = -1e30f, m1r = -1e30f, l0r = 0.f, l1r = 0.f;

    const uint32_t a_off = (uint32_t)(wid * 16 + (lane & 15)) * APAD + (lane >> 4) * 8;
    const uint32_t b_off = (uint32_t)(((lane >> 4) << 3) + (lane & 7)) * APAD
                         + ((lane >> 3) & 1) * 8;
    const int tg = lane & 3;

    for (int cc = 0; cc < CH_PER_SPLIT; cc++) {
        const int key0 = (sp * CH_PER_SPLIT + cc) * 64;
        __syncthreads();   // previous chunk's ks/vst reads complete (Q load on cc==0)

        // K chunk via cp.async: [key][dh]
        {
            const int row = tid >> 1;
            const int cb = (tid & 1) * 4;
            const __half* src = g_kvh + ((size_t)(b * NKEYS) + key0 + row) * (2 * DIM) + h * DH;
            #pragma unroll
            for (int i = 0; i < 4; i++)
                cp_async16(sk + (row * APAD + (cb + i) * 8) * 2, src + (cb + i) * 8);
            cp_commit();
        }
        // V chunk transposed: [dh][key] via half2 (key pair) stores
        {
            const int kp = (tid >> 2) * 2;           // even key
            const int d0 = (tid & 3) * 16;
            const __half* v0 = g_kvh + ((size_t)(b * NKEYS) + key0 + kp) * (2 * DIM)
                             + DIM + h * DH + d0;
            const __half* v1 = v0 + 2 * DIM;
            #pragma unroll
            for (int i = 0; i < 2; i++) {
                uint4 u0 = *reinterpret_cast<const uint4*>(v0 + i * 8);
                uint4 u1 = *reinterpret_cast<const uint4*>(v1 + i * 8);
                const __half* av = reinterpret_cast<const __half*>(&u0);
                const __half* cv = reinterpret_cast<const __half*>(&u1);
                #pragma unroll
                for (int j = 0; j < 8; j++)
                    *reinterpret_cast<__half2*>(vst + (d0 + i * 8 + j) * APAD + kp) =
                        __halves2half2(av[j], cv[j]);
            }
        }
        if (tid < 64) {
            const int kg = key0 + tid;
            bias[tid] = (kg < N1) ? (mask[(size_t)b * N1 + kg] - 1.0f) * 100.0f : 0.f;
        }
        cp_wait<0>();
        __syncthreads();

        // S = Q @ K^T  (m16 x n64 x k64 per warp)
        float s[8][4];
        #pragma unroll
        for (int j = 0; j < 8; j++)
            #pragma unroll
            for (int q = 0; q < 4; q++) s[j][q] = 0.f;
        #pragma unroll
        for (int kk = 0; kk < 4; kk++) {
            uint32_t af[4], bf[8][2];
            ldm_x4(af, sq + (a_off + kk * 16) * 2);
            #pragma unroll
            for (int p = 0; p < 4; p++) {
                uint32_t r4[4];
                ldm_x4(r4, sk + (b_off + (uint32_t)(p * 16) * APAD + kk * 16) * 2);
                bf[2 * p][0]     = r4[0];
                bf[2 * p][1]     = r4[1];
                bf[2 * p + 1][0] = r4[2];
                bf[2 * p + 1][1] = r4[3];
            }
            #pragma unroll
            for (int nt = 0; nt < 8; nt++)
                mma_f16(s[nt], af, bf[nt]);
        }

        // bias + row max
        float c0 = -1e30f, c1 = -1e30f;
        #pragma unroll
        for (int nt = 0; nt < 8; nt++) {
            const float b0 = bias[nt * 8 + 2 * tg];
            const float b1 = bias[nt * 8 + 2 * tg + 1];
            s[nt][0] += b0; s[nt][1] += b1; s[nt][2] += b0; s[nt][3] += b1;
            c0 = fmaxf(c0, fmaxf(s[nt][0], s[nt][1]));
            c1 = fmaxf(c1, fmaxf(s[nt][2], s[nt][3]));
        }
        c0 = fmaxf(c0, __shfl_xor_sync(0xffffffffu, c0, 1));
        c0 = fmaxf(c0, __shfl_xor_sync(0xffffffffu, c0, 2));
        c1 = fmaxf(c1, __shfl_xor_sync(0xffffffffu, c1, 1));
        c1 = fmaxf(c1, __shfl_xor_sync(0xffffffffu, c1, 2));

        const float mn0 = fmaxf(m0r, c0);
        const float mn1 = fmaxf(m1r, c1);
        const float al0 = __expf(m0r - mn0);
        const float al1 = __expf(m1r - mn1);
        float cs0 = 0.f, cs1 = 0.f;
        #pragma unroll
        for (int nt = 0; nt < 8; nt++) {
            s[nt][0] = __expf(s[nt][0] - mn0); cs0 += s[nt][0];
            s[nt][1] = __expf(s[nt][1] - mn0); cs0 += s[nt][1];
            s[nt][2] = __expf(s[nt][2] - mn1); cs1 += s[nt][2];
            s[nt][3] = __expf(s[nt][3] - mn1); cs1 += s[nt][3];
        }
        cs0 += __shfl_xor_sync(0xffffffffu, cs0, 1);
        cs0 += __shfl_xor_sync(0xffffffffu, cs0, 2);
        cs1 += __shfl_xor_sync(0xffffffffu, cs1, 1);
        cs1 += __shfl_xor_sync(0xffffffffu, cs1, 2);
        l0r = l0r * al0 + cs0; m0r = mn0;
        l1r = l1r * al1 + cs1; m1r = mn1;
        #pragma unroll
        for (int nt = 0; nt < 8; nt++) {
            o[nt][0] *= al0; o[nt][1] *= al0;
            o[nt][2] *= al1; o[nt][3] *= al1;
        }

        // P fragments (register reuse) + PV
        #pragma unroll
        for (int kv = 0; kv < 4; kv++) {
            uint32_t pa[4];
            pa[0] = pack_h2(s[2 * kv][0],     s[2 * kv][1]);
            pa[1] = pack_h2(s[2 * kv][2],     s[2 * kv][3]);
            pa[2] = pack_h2(s[2 * kv + 1][0], s[2 * kv + 1][1]);
            pa[3] = pack_h2(s[2 * kv + 1][2], s[2 * kv + 1][3]);
            uint32_t bf[8][2];
            #pragma unroll
            for (int p = 0; p < 4; p++) {
                uint32_t r4[4];
                ldm_x4(r4, sv + (b_off + (uint32_t)(p * 16) * APAD + kv * 16) * 2);
                bf[2 * p][0]     = r4[0];
                bf[2 * p][1]     = r4[1];
                bf[2 * p + 1][0] = r4[2];
                bf[2 * p + 1][1] = r4[3];
            }
            #pragma unroll
            for (int nt = 0; nt < 8; nt++)
                mma_f16(o[nt], pa, bf[nt]);
        }
    }

    // Epilogue: unnormalized partial O + (m, l)
    const int g = lane >> 2;
    const int row0 = wid * 16 + g;
    float* po = g_pO + ((size_t)(bh * NSPLIT + sp) * N2) * DH;
    #pragma unroll
    for (int nt = 0; nt < 8; nt++) {
        *reinterpret_cast<float2*>(po + (size_t)row0 * DH + nt * 8 + 2 * tg) =
            make_float2(o[nt][0], o[nt][1]);
        *reinterpret_cast<float2*>(po + (size_t)(row0 + 8) * DH + nt * 8 + 2 * tg) =
            make_float2(o[nt][2], o[nt][3]);
    }
    if (tg == 0) {
        float* pml = g_pml + (size_t)(bh * NSPLIT + sp) * 2 * N2;
        pml[row0]          = m0r;
        pml[row0 + 8]      = m1r;
        pml[N2 + row0]     = l0r;
        pml[N2 + row0 + 8] = l1r;
    }
}

// ---------------------------------------------------------------------------
// Merge partials -> g_attnh (half)
// ---------------------------------------------------------------------------
__global__ __launch_bounds__(256) void attn_merge()
{
    const int bh = blockIdx.x;
    const int b = bh / HEADS;
    const int h = bh - b * HEADS;
    const int tid = threadIdx.x;
    const int q  = tid >> 2;
    const int dq = tid & 3;

    float ms[NSPLIT], ls[NSPLIT];
    float M = -1e30f;
    #pragma unroll
    for (int s = 0; s < NSPLIT; s++) {
        const float* pml = g_pml + (size_t)(bh * NSPLIT + s) * 2 * N2;
        ms[s] = pml[q];
        ls[s] = pml[N2 + q];
        M = fmaxf(M, ms[s]);
    }
    float w[NSPLIT], lt = 0.f;
    #pragma unroll
    for (int s = 0; s < NSPLIT; s++) {
        w[s] = __expf(ms[s] - M);
        lt += ls[s] * w[s];
    }
    const float inv = 1.0f / lt;

    __half* dst = g_attnh + ((size_t)(b * N2 + q)) * DIM + h * DH + dq * 16;
    #pragma unroll
    for (int j = 0; j < 4; j++) {
        float4 acc = make_float4(0.f, 0.f, 0.f, 0.f);
        #pragma unroll
        for (int s = 0; s < NSPLIT; s++) {
            const float4 v = *reinterpret_cast<const float4*>(
                g_pO + ((size_t)(bh * NSPLIT + s) * N2 + q) * DH + dq * 16 + j * 4);
            acc.x += w[s] * v.x;
            acc.y += w[s] * v.y;
            acc.z += w[s] * v.z;
            acc.w += w[s] * v.w;
        }
        __half2 h0 = make_half2(__float2half_rn(acc.x * inv), __float2half_rn(acc.y * inv));
        __half2 h1 = make_half2(__float2half_rn(acc.z * inv), __float2half_rn(acc.w * inv));
        *reinterpret_cast<__half2*>(dst + j * 4)     = h0;
        *reinterpret_cast<__half2*>(dst + j * 4 + 2) = h1;
    }
}

// ---------------------------------------------------------------------------
// Launch
// ---------------------------------------------------------------------------
extern "C" void kernel_launch(void* const* d_in, const int* in_sizes, int n_in,
                              void* d_out, int out_size)
{
    const float* x       = (const float*)d_in[0];
    const float* latents = (const float*)d_in[1];
    const float* mask    = (const float*)d_in[2];
    const float* ln1g    = (const float*)d_in[3];
    const float* ln1b    = (const float*)d_in[4];
    const float* ln2g    = (const float*)d_in[5];
    const float* ln2b    = (const float*)d_in[6];
    const float* Wq      = (const float*)d_in[7];
    const float* Wkv     = (const float*)d_in[8];
    const float* Wout    = (const float*)d_in[9];
    float* out = (float*)d_out;

    __half *p_kvin, *p_lnh, *p_qh, *p_kvh, *p_attnh, *p_wkvT, *p_wqT, *p_woT;
    cudaGetSymbolAddress((void**)&p_kvin,  g_kvin);
    cudaGetSymbolAddress((void**)&p_lnh,   g_lnh);
    cudaGetSymbolAddress((void**)&p_qh,    g_qh);
    cudaGetSymbolAddress((void**)&p_kvh,   g_kvh);
    cudaGetSymbolAddress((void**)&p_attnh, g_attnh);
    cudaGetSymbolAddress((void**)&p_wkvT,  g_wkvT);
    cudaGetSymbolAddress((void**)&p_wqT,   g_wqT);
    cudaGetSymbolAddress((void**)&p_woT,   g_woT);

    static bool attr_set = false;
    if (!attr_set) {
        cudaFuncSetAttribute(gemm_tc<__half>, cudaFuncAttributeMaxDynamicSharedMemorySize,
                             GEMM_SMEM_BYTES);
        cudaFuncSetAttribute(gemm_tc_s<__half>, cudaFuncAttributeMaxDynamicSharedMemorySize,
                             GEMM_S_SMEM_BYTES);
        cudaFuncSetAttribute(gemm_tc_s<float>, cudaFuncAttributeMaxDynamicSharedMemorySize,
                             GEMM_S_SMEM_BYTES);
        attr_set = true;
    }

    // 0) Transpose + fp16-round weights
    transpose_kernel<<<dim3(2 * DIM / 32, DIM / 32), dim3(32, 8)>>>(Wkv, p_wkvT, 2 * DIM);
    transpose_kernel<<<dim3(DIM / 32, DIM / 32), dim3(32, 8)>>>(Wq, p_wqT, DIM);
    transpose_kernel<<<dim3(DIM / 32, DIM / 32), dim3(32, 8)>>>(Wout, p_woT, DIM);

    // 1) LayerNorms (half outputs)
    ln_kernel<<<MROWS, 256>>>(x, latents, ln1g, ln1b, ln2g, ln2b);

    // 2) KV GEMM (fp16 mma, half output)
    gemm_tc<__half><<<dim3(2 * DIM / 128, MROWS / 128), 256, GEMM_SMEM_BYTES>>>(
        p_kvin, p_wkvT, p_kvh, 2 * DIM);

    // 3) Q GEMM (small tiles, half output)
    gemm_tc_s<__half><<<dim3(DIM / 64, BATCH * N2 / 64), 256, GEMM_S_SMEM_BYTES>>>(
        p_lnh, p_wqT, p_qh, DIM);

    // 4) Attention: fp16-MMA split-K partials + merge
    attn_partial<<<dim3(HEADS, BATCH, NSPLIT), 128>>>(mask);
    attn_merge<<<BATCH * HEADS, 256>>>();

    // 5) Out GEMM (small tiles, float output) -> d_out
    gemm_tc_s<float><<<dim3(DIM / 64, BATCH * N2 / 64), 256, GEMM_S_SMEM_BYTES>>>(
        p_attnh, p_woT, out, DIM);
}

// round 10
// speedup vs baseline: 1.6271x; 1.0265x over previous
#include <cuda_runtime.h>
#include <cuda_fp16.h>
#include <cstdint>

// ---------------------------------------------------------------------------
// PerceiverAttention, sm_103 — Round 9:
//   * attn_partial: V loaded [key][dh] via cp.async + ldmatrix.x4.trans
//     (scalar V transpose removed)
//   * ln_kernel: 2 rows/block, 2x float4 per thread (MLP=2)
// ---------------------------------------------------------------------------

#define BATCH 8
#define N1 4096
#define N2 64
#define NKEYS 4160
#define DIM 1024
#define HEADS 16
#define DH 64
#define MROWS (BATCH * NKEYS)   // 33280
#define NSPLIT 5
#define CH_PER_SPLIT 13

__device__ __half g_kvin[(size_t)MROWS * DIM];
__device__ __half g_lnh [(size_t)BATCH * N2 * DIM];
__device__ __half g_qh  [(size_t)BATCH * N2 * DIM];
__device__ __half g_kvh [(size_t)MROWS * 2 * DIM];
__device__ __half g_attnh[(size_t)BATCH * N2 * DIM];
__device__ __half g_wkvT[(size_t)2 * DIM * DIM];
__device__ __half g_wqT [(size_t)DIM * DIM];
__device__ __half g_woT [(size_t)DIM * DIM];
__device__ float  g_pO  [(size_t)BATCH * HEADS * NSPLIT * N2 * DH];
__device__ float  g_pml [(size_t)BATCH * HEADS * NSPLIT * 2 * N2];

// ---------------------------------------------------------------------------
// Helpers
// ---------------------------------------------------------------------------
__device__ __forceinline__ uint32_t smem_u32(const void* p) {
    uint32_t a;
    asm("{ .reg .u64 t; cvta.to.shared.u64 t, %1; cvt.u32.u64 %0, t; }" : "=r"(a) : "l"(p));
    return a;
}
__device__ __forceinline__ void cp_async16(uint32_t dst, const void* src) {
    asm volatile("cp.async.cg.shared.global [%0], [%1], 16;" :: "r"(dst), "l"(src));
}
__device__ __forceinline__ void cp_commit() {
    asm volatile("cp.async.commit_group;" ::: "memory");
}
template <int N>
__device__ __forceinline__ void cp_wait() {
    asm volatile("cp.async.wait_group %0;" :: "n"(N) : "memory");
}
__device__ __forceinline__ void mma_f16(float* d, const uint32_t* a, const uint32_t* b) {
    asm volatile(
        "mma.sync.aligned.m16n8k16.row.col.f32.f16.f16.f32 "
        "{%0,%1,%2,%3}, {%4,%5,%6,%7}, {%8,%9}, {%0,%1,%2,%3};"
        : "+f"(d[0]), "+f"(d[1]), "+f"(d[2]), "+f"(d[3])
        : "r"(a[0]), "r"(a[1]), "r"(a[2]), "r"(a[3]), "r"(b[0]), "r"(b[1]));
}
__device__ __forceinline__ void ldm_x4(uint32_t* r, uint32_t addr) {
    asm volatile("ldmatrix.sync.aligned.m8n8.x4.shared.b16 {%0,%1,%2,%3}, [%4];"
        : "=r"(r[0]), "=r"(r[1]), "=r"(r[2]), "=r"(r[3]) : "r"(addr));
}
__device__ __forceinline__ void ldm_x4_t(uint32_t* r, uint32_t addr) {
    asm volatile("ldmatrix.sync.aligned.m8n8.x4.trans.shared.b16 {%0,%1,%2,%3}, [%4];"
        : "=r"(r[0]), "=r"(r[1]), "=r"(r[2]), "=r"(r[3]) : "r"(addr));
}
__device__ __forceinline__ uint32_t pack_h2(float a, float b) {
    __half2 h = __floats2half2_rn(a, b);
    return *reinterpret_cast<uint32_t*>(&h);
}
__device__ __forceinline__ void store_pair(float* p, float a, float b) {
    *reinterpret_cast<float2*>(p) = make_float2(a, b);
}
__device__ __forceinline__ void store_pair(__half* p, float a, float b) {
    *reinterpret_cast<__half2*>(p) = make_half2(__float2half_rn(a), __float2half_rn(b));
}

// ---------------------------------------------------------------------------
// Weight transpose + fp16 round
// ---------------------------------------------------------------------------
__global__ __launch_bounds__(256) void transpose_kernel(
    const float* __restrict__ in, __half* __restrict__ out, int ncols)
{
    __shared__ float t[32][33];
    const int bx = blockIdx.x * 32;
    const int by = blockIdx.y * 32;
    const int x = threadIdx.x;
    const int y = threadIdx.y;
    #pragma unroll
    for (int i = 0; i < 32; i += 8)
        t[y + i][x] = in[(size_t)(by + y + i) * ncols + bx + x];
    __syncthreads();
    #pragma unroll
    for (int i = 0; i < 32; i += 8)
        out[(size_t)(bx + y + i) * DIM + by + x] = __float2half_rn(t[x][y + i]);
}

// ---------------------------------------------------------------------------
// LayerNorm -> half outputs. 2 rows per block; 128 threads/row, 8 floats each.
// ---------------------------------------------------------------------------
__global__ __launch_bounds__(256) void ln_kernel(
    const float* __restrict__ x, const float* __restrict__ lat,
    const float* __restrict__ g1, const float* __restrict__ b1,
    const float* __restrict__ g2, const float* __restrict__ b2)
{
    __shared__ float red[16];   // [warp][{s,sq}]
    const int half = threadIdx.x >> 7;            // which row of the pair
    const int tl   = threadIdx.x & 127;
    const int wid  = threadIdx.x >> 5;            // 0..7
    const int lane = threadIdx.x & 31;

    const int r  = blockIdx.x * 2 + half;
    const int bb = r / NKEYS;
    const int i  = r - bb * NKEYS;

    const float* src;
    const float* g;
    const float* be;
    __half* dst2 = nullptr;
    if (i < N1) {
        src = x + ((size_t)bb * N1 + i) * DIM;
        g = g1; be = b1;
    } else {
        const int j = i - N1;
        src = lat + ((size_t)bb * N2 + j) * DIM;
        g = g2; be = b2;
        dst2 = g_lnh + ((size_t)bb * N2 + j) * DIM;
    }
    __half* dst = g_kvin + (size_t)r * DIM;

    const float4* s4 = reinterpret_cast<const float4*>(src);
    float4 v0 = s4[tl * 2];
    float4 v1 = s4[tl * 2 + 1];
    float s  = v0.x + v0.y + v0.z + v0.w + v1.x + v1.y + v1.z + v1.w;
    float sq = v0.x*v0.x + v0.y*v0.y + v0.z*v0.z + v0.w*v0.w
             + v1.x*v1.x + v1.y*v1.y + v1.z*v1.z + v1.w*v1.w;
    #pragma unroll
    for (int o = 16; o > 0; o >>= 1) {
        s  += __shfl_xor_sync(0xffffffffu, s, o);
        sq += __shfl_xor_sync(0xffffffffu, sq, o);
    }
    if (lane == 0) { red[wid * 2] = s; red[wid * 2 + 1] = sq; }
    __syncthreads();
    const int wb = half * 4;
    float S  = red[(wb+0)*2] + red[(wb+1)*2] + red[(wb+2)*2] + red[(wb+3)*2];
    float SQ = red[(wb+0)*2+1] + red[(wb+1)*2+1] + red[(wb+2)*2+1] + red[(wb+3)*2+1];

    const float mu   = S * (1.0f / DIM);
    const float var  = SQ * (1.0f / DIM) - mu * mu;
    const float rstd = rsqrtf(var + 1e-5f);

    const float4* g4 = reinterpret_cast<const float4*>(g);
    const float4* b4 = reinterpret_cast<const float4*>(be);
    float4 gv0 = g4[tl * 2], gv1 = g4[tl * 2 + 1];
    float4 bv0 = b4[tl * 2], bv1 = b4[tl * 2 + 1];

    uint4 u;
    __half2* hp = reinterpret_cast<__half2*>(&u);
    hp[0] = make_half2(__float2half_rn((v0.x - mu) * rstd * gv0.x + bv0.x),
                       __float2half_rn((v0.y - mu) * rstd * gv0.y + bv0.y));
    hp[1] = make_half2(__float2half_rn((v0.z - mu) * rstd * gv0.z + bv0.z),
                       __float2half_rn((v0.w - mu) * rstd * gv0.w + bv0.w));
    hp[2] = make_half2(__float2half_rn((v1.x - mu) * rstd * gv1.x + bv1.x),
                       __float2half_rn((v1.y - mu) * rstd * gv1.y + bv1.y));
    hp[3] = make_half2(__float2half_rn((v1.z - mu) * rstd * gv1.z + bv1.z),
                       __float2half_rn((v1.w - mu) * rstd * gv1.w + bv1.w));
    reinterpret_cast<uint4*>(dst)[tl] = u;
    if (dst2) reinterpret_cast<uint4*>(dst2)[tl] = u;
}

// ---------------------------------------------------------------------------
// fp16 mma.sync GEMM (128x128 tile)
// ---------------------------------------------------------------------------
#define PADH 72
#define TILE_H (128 * PADH)
#define NSTAGE 3
#define GEMM_SMEM_BYTES (NSTAGE * 2 * TILE_H * 2)   // 110592

template <typename OutT>
__global__ __launch_bounds__(256, 2) void gemm_tc(
    const __half* __restrict__ A, const __half* __restrict__ Bt,
    OutT* __restrict__ C, int ldc)
{
    extern __shared__ __half smh[];
    const uint32_t sb = smem_u32(smh);

    const int tid  = threadIdx.x;
    const int wid  = tid >> 5;
    const int lane = tid & 31;
    const int wm = wid & 3;
    const int wn = wid >> 2;
    const int m0 = blockIdx.y * 128;
    const int n0 = blockIdx.x * 128;

    const __half* ga = A  + (size_t)m0 * DIM;
    const __half* gb = Bt + (size_t)n0 * DIM;

    const int lr = tid >> 3;
    const int lc = tid & 7;

    float acc[2][8][4];
    #pragma unroll
    for (int i = 0; i < 2; i++)
        #pragma unroll
        for (int j = 0; j < 8; j++)
            #pragma unroll
            for (int q = 0; q < 4; q++) acc[i][j][q] = 0.f;

    const uint32_t a_off = (uint32_t)(wm * 32 + (lane & 15)) * PADH + (lane >> 4) * 8;
    const uint32_t b_off = (uint32_t)(wn * 64 + ((lane >> 4) << 3) + (lane & 7)) * PADH
                         + ((lane >> 3) & 1) * 8;

    auto load_tile = [&](int chunk, int stage) {
        const uint32_t abase = sb + (uint32_t)stage * 2 * TILE_H * 2;
        const uint32_t bbase = abase + TILE_H * 2;
        const int k0 = chunk * 64;
        #pragma unroll
        for (int i = 0; i < 4; i++) {
            const int r = lr + i * 32;
            cp_async16(abase + (r * PADH + lc * 8) * 2, ga + (size_t)r * DIM + k0 + lc * 8);
        }
        #pragma unroll
        for (int i = 0; i < 4; i++) {
            const int r = lr + i * 32;
            cp_async16(bbase + (r * PADH + lc * 8) * 2, gb + (size_t)r * DIM + k0 + lc * 8);
        }
        cp_commit();
    };

    const int NCHUNK = DIM / 64;   // 16
    load_tile(0, 0);
    load_tile(1, 1);

    for (int c = 0; c < NCHUNK; c++) {
        const int stage = c % NSTAGE;
        if (c + 2 < NCHUNK) { load_tile(c + 2, (c + 2) % NSTAGE); cp_wait<1>(); }
        else                { cp_wait<0>(); }
        __syncthreads();

        const uint32_t sA = sb + (uint32_t)stage * 2 * TILE_H * 2;
        const uint32_t sB = sA + TILE_H * 2;

        #pragma unroll
        for (int kk = 0; kk < 4; kk++) {
            uint32_t af[2][4], bf[8][2];
            #pragma unroll
            for (int mt = 0; mt < 2; mt++)
                ldm_x4(af[mt], sA + (a_off + (uint32_t)(mt * 16) * PADH + kk * 16) * 2);
            #pragma unroll
            for (int p = 0; p < 4; p++) {
                uint32_t r4[4];
                ldm_x4(r4, sB + (b_off + (uint32_t)(p * 16) * PADH + kk * 16) * 2);
                bf[2 * p][0]     = r4[0];
                bf[2 * p][1]     = r4[1];
                bf[2 * p + 1][0] = r4[2];
                bf[2 * p + 1][1] = r4[3];
            }
            #pragma unroll
            for (int mt = 0; mt < 2; mt++)
                #pragma unroll
                for (int nt = 0; nt < 8; nt++)
                    mma_f16(acc[mt][nt], af[mt], bf[nt]);
        }
        __syncthreads();
    }

    #pragma unroll
    for (int mt = 0; mt < 2; mt++) {
        const int row = m0 + wm * 32 + mt * 16 + (lane >> 2);
        #pragma unroll
        for (int nt = 0; nt < 8; nt++) {
            const int col = n0 + wn * 64 + nt * 8 + (lane & 3) * 2;
            store_pair(C + (size_t)row * ldc + col, acc[mt][nt][0], acc[mt][nt][1]);
            store_pair(C + (size_t)(row + 8) * ldc + col, acc[mt][nt][2], acc[mt][nt][3]);
        }
    }
}

// ---------------------------------------------------------------------------
// Small-tile fp16 GEMM (64x64 CTA tile) for 512-row GEMMs
// ---------------------------------------------------------------------------
#define TILE_HS (64 * PADH)
#define GEMM_S_SMEM_BYTES (NSTAGE * 2 * TILE_HS * 2)   // 55296

template <typename OutT>
__global__ __launch_bounds__(256, 2) void gemm_tc_s(
    const __half* __restrict__ A, const __half* __restrict__ Bt,
    OutT* __restrict__ C, int ldc)
{
    extern __shared__ __half smh[];
    const uint32_t sb = smem_u32(smh);

    const int tid  = threadIdx.x;
    const int wid  = tid >> 5;
    const int lane = tid & 31;
    const int wm = wid & 3;
    const int wn = wid >> 2;
    const int m0 = blockIdx.y * 64;
    const int n0 = blockIdx.x * 64;

    const __half* ga = A  + (size_t)m0 * DIM;
    const __half* gb = Bt + (size_t)n0 * DIM;

    const int lr = tid >> 3;
    const int lc = tid & 7;

    float acc[4][4];
    #pragma unroll
    for (int j = 0; j < 4; j++)
        #pragma unroll
        for (int q = 0; q < 4; q++) acc[j][q] = 0.f;

    const uint32_t a_off = (uint32_t)(wm * 16 + (lane & 15)) * PADH + (lane >> 4) * 8;
    const uint32_t b_off = (uint32_t)(wn * 32 + ((lane >> 4) << 3) + (lane & 7)) * PADH
                         + ((lane >> 3) & 1) * 8;

    auto load_tile = [&](int chunk, int stage) {
        const uint32_t abase = sb + (uint32_t)stage * 2 * TILE_HS * 2;
        const uint32_t bbase = abase + TILE_HS * 2;
        const int k0 = chunk * 64;
        #pragma unroll
        for (int i = 0; i < 2; i++) {
            const int r = lr + i * 32;
            cp_async16(abase + (r * PADH + lc * 8) * 2, ga + (size_t)r * DIM + k0 + lc * 8);
        }
        #pragma unroll
        for (int i = 0; i < 2; i++) {
            const int r = lr + i * 32;
            cp_async16(bbase + (r * PADH + lc * 8) * 2, gb + (size_t)r * DIM + k0 + lc * 8);
        }
        cp_commit();
    };

    const int NCHUNK = DIM / 64;
    load_tile(0, 0);
    load_tile(1, 1);

    for (int c = 0; c < NCHUNK; c++) {
        const int stage = c % NSTAGE;
        if (c + 2 < NCHUNK) { load_tile(c + 2, (c + 2) % NSTAGE); cp_wait<1>(); }
        else                { cp_wait<0>(); }
        __syncthreads();

        const uint32_t sA = sb + (uint32_t)stage * 2 * TILE_HS * 2;
        const uint32_t sB = sA + TILE_HS * 2;

        #pragma unroll
        for (int kk = 0; kk < 4; kk++) {
            uint32_t af[4], bf[4][2];
            ldm_x4(af, sA + (a_off + kk * 16) * 2);
            #pragma unroll
            for (int p = 0; p < 2; p++) {
                uint32_t r4[4];
                ldm_x4(r4, sB + (b_off + (uint32_t)(p * 16) * PADH + kk * 16) * 2);
                bf[2 * p][0]     = r4[0];
                bf[2 * p][1]     = r4[1];
                bf[2 * p + 1][0] = r4[2];
                bf[2 * p + 1][1] = r4[3];
            }
            #pragma unroll
            for (int nt = 0; nt < 4; nt++)
                mma_f16(acc[nt], af, bf[nt]);
        }
        __syncthreads();
    }

    const int row = m0 + wm * 16 + (lane >> 2);
    #pragma unroll
    for (int nt = 0; nt < 4; nt++) {
        const int col = n0 + wn * 32 + nt * 8 + (lane & 3) * 2;
        store_pair(C + (size_t)row * ldc + col, acc[nt][0], acc[nt][1]);
        store_pair(C + (size_t)(row + 8) * ldc + col, acc[nt][2], acc[nt][3]);
    }
}

// ---------------------------------------------------------------------------
// Split-K flash attention on fp16 mma.sync.
// Grid (HEADS, BATCH, NSPLIT), 128 threads (4 warps; warp = 16 query rows).
// K and V both [key][dh] via cp.async; V fragments via ldmatrix.trans.
// ---------------------------------------------------------------------------
#define APAD 72

__global__ __launch_bounds__(128) void attn_partial(const float* __restrict__ mask)
{
    __shared__ __half qs [64 * APAD];   // [query][dh]
    __shared__ __half ks [64 * APAD];   // [key][dh]
    __shared__ __half vsk[64 * APAD];   // [key][dh]
    __shared__ float bias[64];

    const int h = blockIdx.x;
    const int b = blockIdx.y;
    const int sp = blockIdx.z;
    const int bh = b * HEADS + h;
    const int tid = threadIdx.x;
    const int wid = tid >> 5;
    const int lane = tid & 31;
    const uint32_t sq = smem_u32(qs);
    const uint32_t sk = smem_u32(ks);
    const uint32_t sv = smem_u32(vsk);

    // Load Q (x 0.125), row-major [query][dh]
    {
        const int q = tid >> 1;
        const int d0 = (tid & 1) * 32;
        const uint4* src = reinterpret_cast<const uint4*>(
            g_qh + (size_t)(b * N2 + q) * DIM + h * DH + d0);
        const __half2 s2 = __half2half2(__float2half(0.125f));
        #pragma unroll
        for (int i = 0; i < 4; i++) {
            uint4 u = src[i];
            __half2* hp = reinterpret_cast<__half2*>(&u);
            #pragma unroll
            for (int j = 0; j < 4; j++) hp[j] = __hmul2(hp[j], s2);
            *reinterpret_cast<uint4*>(qs + q * APAD + d0 + i * 8) = u;
        }
    }

    float o[8][4];
    #pragma unroll
    for (int j = 0; j < 8; j++)
        #pragma unroll
        for (int q = 0; q < 4; q++) o[j][q] = 0.f;
    float m0r = -1e30f, m1r = -1e30f, l0r = 0.f, l1r = 0.f;

    const uint32_t a_off = (uint32_t)(wid * 16 + (lane & 15)) * APAD + (lane >> 4) * 8;
    const uint32_t b_off = (uint32_t)(((lane >> 4) << 3) + (lane & 7)) * APAD
                         + ((lane >> 3) & 1) * 8;
    // trans fragment base: row = ((lane>>3)&1)*8 + (lane&7), col = (lane>>4)*8
    const uint32_t t_off = (uint32_t)(((lane >> 3) & 1) * 8 + (lane & 7)) * APAD
                         + (lane >> 4) * 8;
    const int tg = lane & 3;

    for (int cc = 0; cc < CH_PER_SPLIT; cc++) {
        const int key0 = (sp * CH_PER_SPLIT + cc) * 64;
        __syncthreads();   // previous chunk's ks/vsk reads complete (Q load on cc==0)

        // K and V chunks via cp.async: both [key][dh]
        {
            const int row = tid >> 1;
            const int cb = (tid & 1) * 4;
            const __half* ksrc = g_kvh + ((size_t)(b * NKEYS) + key0 + row) * (2 * DIM) + h * DH;
            const __half* vsrc = ksrc + DIM;
            #pragma unroll
            for (int i = 0; i < 4; i++)
                cp_async16(sk + (row * APAD + (cb + i) * 8) * 2, ksrc + (cb + i) * 8);
            #pragma unroll
            for (int i = 0; i < 4; i++)
                cp_async16(sv + (row * APAD + (cb + i) * 8) * 2, vsrc + (cb + i) * 8);
            cp_commit();
        }
        if (tid < 64) {
            const int kg = key0 + tid;
            bias[tid] = (kg < N1) ? (mask[(size_t)b * N1 + kg] - 1.0f) * 100.0f : 0.f;
        }
        cp_wait<0>();
        __syncthreads();

        // S = Q @ K^T  (m16 x n64 x k64 per warp)
        float s[8][4];
        #pragma unroll
        for (int j = 0; j < 8; j++)
            #pragma unroll
            for (int q = 0; q < 4; q++) s[j][q] = 0.f;
        #pragma unroll
        for (int kk = 0; kk < 4; kk++) {
            uint32_t af[4], bf[8][2];
            ldm_x4(af, sq + (a_off + kk * 16) * 2);
            #pragma unroll
            for (int p = 0; p < 4; p++) {
                uint32_t r4[4];
                ldm_x4(r4, sk + (b_off + (uint32_t)(p * 16) * APAD + kk * 16) * 2);
                bf[2 * p][0]     = r4[0];
                bf[2 * p][1]     = r4[1];
                bf[2 * p + 1][0] = r4[2];
                bf[2 * p + 1][1] = r4[3];
            }
            #pragma unroll
            for (int nt = 0; nt < 8; nt++)
                mma_f16(s[nt], af, bf[nt]);
        }

        // bias + row max
        float c0 = -1e30f, c1 = -1e30f;
        #pragma unroll
        for (int nt = 0; nt < 8; nt++) {
            const float b0 = bias[nt * 8 + 2 * tg];
            const float b1 = bias[nt * 8 + 2 * tg + 1];
            s[nt][0] += b0; s[nt][1] += b1; s[nt][2] += b0; s[nt][3] += b1;
            c0 = fmaxf(c0, fmaxf(s[nt][0], s[nt][1]));
            c1 = fmaxf(c1, fmaxf(s[nt][2], s[nt][3]));
        }
        c0 = fmaxf(c0, __shfl_xor_sync(0xffffffffu, c0, 1));
        c0 = fmaxf(c0, __shfl_xor_sync(0xffffffffu, c0, 2));
        c1 = fmaxf(c1, __shfl_xor_sync(0xffffffffu, c1, 1));
        c1 = fmaxf(c1, __shfl_xor_sync(0xffffffffu, c1, 2));

        const float mn0 = fmaxf(m0r, c0);
        const float mn1 = fmaxf(m1r, c1);
        const float al0 = __expf(m0r - mn0);
        const float al1 = __expf(m1r - mn1);
        float cs0 = 0.f, cs1 = 0.f;
        #pragma unroll
        for (int nt = 0; nt < 8; nt++) {
            s[nt][0] = __expf(s[nt][0] - mn0); cs0 += s[nt][0];
            s[nt][1] = __expf(s[nt][1] - mn0); cs0 += s[nt][1];
            s[nt][2] = __expf(s[nt][2] - mn1); cs1 += s[nt][2];
            s[nt][3] = __expf(s[nt][3] - mn1); cs1 += s[nt][3];
        }
        cs0 += __shfl_xor_sync(0xffffffffu, cs0, 1);
        cs0 += __shfl_xor_sync(0xffffffffu, cs0, 2);
        cs1 += __shfl_xor_sync(0xffffffffu, cs1, 1);
        cs1 += __shfl_xor_sync(0xffffffffu, cs1, 2);
        l0r = l0r * al0 + cs0; m0r = mn0;
        l1r = l1r * al1 + cs1; m1r = mn1;
        #pragma unroll
        for (int nt = 0; nt < 8; nt++) {
            o[nt][0] *= al0; o[nt][1] *= al0;
            o[nt][2] *= al1; o[nt][3] *= al1;
        }

        // P fragments (register reuse) + PV with ldmatrix.trans V fragments
        #pragma unroll
        for (int kv = 0; kv < 4; kv++) {
            uint32_t pa[4];
            pa[0] = pack_h2(s[2 * kv][0],     s[2 * kv][1]);
            pa[1] = pack_h2(s[2 * kv][2],     s[2 * kv][3]);
            pa[2] = pack_h2(s[2 * kv + 1][0], s[2 * kv + 1][1]);
            pa[3] = pack_h2(s[2 * kv + 1][2], s[2 * kv + 1][3]);
            uint32_t bf[8][2];
            #pragma unroll
            for (int p = 0; p < 4; p++) {
                uint32_t r4[4];
                ldm_x4_t(r4, sv + (t_off + (uint32_t)(kv * 16) * APAD + p * 16) * 2);
                bf[2 * p][0]     = r4[0];
                bf[2 * p][1]     = r4[1];
                bf[2 * p + 1][0] = r4[2];
                bf[2 * p + 1][1] = r4[3];
            }
            #pragma unroll
            for (int nt = 0; nt < 8; nt++)
                mma_f16(o[nt], pa, bf[nt]);
        }
    }

    // Epilogue: unnormalized partial O + (m, l)
    const int g = lane >> 2;
    const int row0 = wid * 16 + g;
    float* po = g_pO + ((size_t)(bh * NSPLIT + sp) * N2) * DH;
    #pragma unroll
    for (int nt = 0; nt < 8; nt++) {
        *reinterpret_cast<float2*>(po + (size_t)row0 * DH + nt * 8 + 2 * tg) =
            make_float2(o[nt][0], o[nt][1]);
        *reinterpret_cast<float2*>(po + (size_t)(row0 + 8) * DH + nt * 8 + 2 * tg) =
            make_float2(o[nt][2], o[nt][3]);
    }
    if (tg == 0) {
        float* pml = g_pml + (size_t)(bh * NSPLIT + sp) * 2 * N2;
        pml[row0]          = m0r;
        pml[row0 + 8]      = m1r;
        pml[N2 + row0]     = l0r;
        pml[N2 + row0 + 8] = l1r;
    }
}

// ---------------------------------------------------------------------------
// Merge partials -> g_attnh (half)
// ---------------------------------------------------------------------------
__global__ __launch_bounds__(256) void attn_merge()
{
    const int bh = blockIdx.x;
    const int b = bh / HEADS;
    const int h = bh - b * HEADS;
    const int tid = threadIdx.x;
    const int q  = tid >> 2;
    const int dq = tid & 3;

    float ms[NSPLIT], ls[NSPLIT];
    float M = -1e30f;
    #pragma unroll
    for (int s = 0; s < NSPLIT; s++) {
        const float* pml = g_pml + (size_t)(bh * NSPLIT + s) * 2 * N2;
        ms[s] = pml[q];
        ls[s] = pml[N2 + q];
        M = fmaxf(M, ms[s]);
    }
    float w[NSPLIT], lt = 0.f;
    #pragma unroll
    for (int s = 0; s < NSPLIT; s++) {
        w[s] = __expf(ms[s] - M);
        lt += ls[s] * w[s];
    }
    const float inv = 1.0f / lt;

    __half* dst = g_attnh + ((size_t)(b * N2 + q)) * DIM + h * DH + dq * 16;
    #pragma unroll
    for (int j = 0; j < 4; j++) {
        float4 acc = make_float4(0.f, 0.f, 0.f, 0.f);
        #pragma unroll
        for (int s = 0; s < NSPLIT; s++) {
            const float4 v = *reinterpret_cast<const float4*>(
                g_pO + ((size_t)(bh * NSPLIT + s) * N2 + q) * DH + dq * 16 + j * 4);
            acc.x += w[s] * v.x;
            acc.y += w[s] * v.y;
            acc.z += w[s] * v.z;
            acc.w += w[s] * v.w;
        }
        __half2 h0 = make_half2(__float2half_rn(acc.x * inv), __float2half_rn(acc.y * inv));
        __half2 h1 = make_half2(__float2half_rn(acc.z * inv), __float2half_rn(acc.w * inv));
        *reinterpret_cast<__half2*>(dst + j * 4)     = h0;
        *reinterpret_cast<__half2*>(dst + j * 4 + 2) = h1;
    }
}

// ---------------------------------------------------------------------------
// Launch
// ---------------------------------------------------------------------------
extern "C" void kernel_launch(void* const* d_in, const int* in_sizes, int n_in,
                              void* d_out, int out_size)
{
    const float* x       = (const float*)d_in[0];
    const float* latents = (const float*)d_in[1];
    const float* mask    = (const float*)d_in[2];
    const float* ln1g    = (const float*)d_in[3];
    const float* ln1b    = (const float*)d_in[4];
    const float* ln2g    = (const float*)d_in[5];
    const float* ln2b    = (const float*)d_in[6];
    const float* Wq      = (const float*)d_in[7];
    const float* Wkv     = (const float*)d_in[8];
    const float* Wout    = (const float*)d_in[9];
    float* out = (float*)d_out;

    __half *p_kvin, *p_lnh, *p_qh, *p_kvh, *p_attnh, *p_wkvT, *p_wqT, *p_woT;
    cudaGetSymbolAddress((void**)&p_kvin,  g_kvin);
    cudaGetSymbolAddress((void**)&p_lnh,   g_lnh);
    cudaGetSymbolAddress((void**)&p_qh,    g_qh);
    cudaGetSymbolAddress((void**)&p_kvh,   g_kvh);
    cudaGetSymbolAddress((void**)&p_attnh, g_attnh);
    cudaGetSymbolAddress((void**)&p_wkvT,  g_wkvT);
    cudaGetSymbolAddress((void**)&p_wqT,   g_wqT);
    cudaGetSymbolAddress((void**)&p_woT,   g_woT);

    static bool attr_set = false;
    if (!attr_set) {
        cudaFuncSetAttribute(gemm_tc<__half>, cudaFuncAttributeMaxDynamicSharedMemorySize,
                             GEMM_SMEM_BYTES);
        cudaFuncSetAttribute(gemm_tc_s<__half>, cudaFuncAttributeMaxDynamicSharedMemorySize,
                             GEMM_S_SMEM_BYTES);
        cudaFuncSetAttribute(gemm_tc_s<float>, cudaFuncAttributeMaxDynamicSharedMemorySize,
                             GEMM_S_SMEM_BYTES);
        attr_set = true;
    }

    // 0) Transpose + fp16-round weights
    transpose_kernel<<<dim3(2 * DIM / 32, DIM / 32), dim3(32, 8)>>>(Wkv, p_wkvT, 2 * DIM);
    transpose_kernel<<<dim3(DIM / 32, DIM / 32), dim3(32, 8)>>>(Wq, p_wqT, DIM);
    transpose_kernel<<<dim3(DIM / 32, DIM / 32), dim3(32, 8)>>>(Wout, p_woT, DIM);

    // 1) LayerNorms (half outputs; 2 rows per block)
    ln_kernel<<<MROWS / 2, 256>>>(x, latents, ln1g, ln1b, ln2g, ln2b);

    // 2) KV GEMM (fp16 mma, half output)
    gemm_tc<__half><<<dim3(2 * DIM / 128, MROWS / 128), 256, GEMM_SMEM_BYTES>>>(
        p_kvin, p_wkvT, p_kvh, 2 * DIM);

    // 3) Q GEMM (small tiles, half output)
    gemm_tc_s<__half><<<dim3(DIM / 64, BATCH * N2 / 64), 256, GEMM_S_SMEM_BYTES>>>(
        p_lnh, p_wqT, p_qh, DIM);

    // 4) Attention: fp16-MMA split-K partials + merge
    attn_partial<<<dim3(HEADS, BATCH, NSPLIT), 128>>>(mask);
    attn_merge<<<BATCH * HEADS, 256>>>();

    // 5) Out GEMM (small tiles, float output) -> d_out
    gemm_tc_s<float><<<dim3(DIM / 64, BATCH * N2 / 64), 256, GEMM_S_SMEM_BYTES>>>(
        p_attnh, p_woT, out, DIM);
}